// round 12
// baseline (speedup 1.0000x reference)
#include <cuda_runtime.h>
#include <cuda_bf16.h>
#include <cstdint>
#include <math.h>

#define HD    256
#define LSEQ  50
#define SSEQ  50
#define NBATCH 64
#define MAXF  32
#define NSEQ  (NBATCH*MAXF)            // 2048
#define MTOT  (NSEQ*LSEQ)              // 102400
#define G3    (3*HD)                   // 768
#define NT_Q  (16*LSEQ*8)              // 6400 GEMM tiles per layer

// ---------------- device scratch ----------------
__device__ __nv_bfloat16  g_Hh[2][NSEQ*HD];
__device__ __nv_bfloat16  g_Hl[2][NSEQ*HD];
__device__ float          g_GI[(size_t)MTOT*G3];    // layer-0 pre-activations
__device__ float          g_GI2[(size_t)MTOT*G3];   // layer-1 pre-activations
__device__ __nv_bfloat16  g_FXh[(size_t)MTOT*HD];
__device__ __nv_bfloat16  g_FXl[(size_t)MTOT*HD];
__device__ __nv_bfloat16  g_X1h[(size_t)MTOT*HD];
__device__ __nv_bfloat16  g_X1l[(size_t)MTOT*HD];
__device__ __nv_bfloat16  g_Wh[4][G3*HD];           // Wih0,Whh0,Wih1,Whh1 (hi)
__device__ __nv_bfloat16  g_Wl[4][G3*HD];
__device__ float g_FL[NSEQ*HD];
__device__ float g_CAT[NSEQ*2*HD];
__device__ float g_SF[NSEQ*HD];
__device__ float g_V[NSEQ*HD];
__device__ float g_TF[NSEQ];
__device__ unsigned g_cnt[16];            // L0 rowgroup step counters (gate L1 tiles)
__device__ unsigned g_q0, g_q1;           // GEMM tile queues (layer 0 / 1)
__device__ unsigned g_c0[16*LSEQ];        // per-(sg,t) GI tile-ready counters L0
__device__ unsigned g_c1[16*LSEQ];        // L1
__device__ int g_perm[NSEQ];
__device__ int g_gmax[16];

// ---------------- helpers ----------------
__device__ __forceinline__ float fast_sigmoid(float x){
    return __fdividef(1.f, 1.f + __expf(-x));
}
__device__ __forceinline__ float fast_tanh(float x){
    return 1.f - __fdividef(2.f, __expf(2.f*x) + 1.f);
}
__device__ __forceinline__ float softplus_f(float x){
    return (x > 20.f) ? x : log1pf(expf(x));
}
__device__ __forceinline__ float2 ffma2(float2 a, float2 b, float2 c){
    unsigned long long ua = reinterpret_cast<unsigned long long&>(a);
    unsigned long long ub = reinterpret_cast<unsigned long long&>(b);
    unsigned long long uc = reinterpret_cast<unsigned long long&>(c);
    unsigned long long ud;
    asm("fma.rn.f32x2 %0, %1, %2, %3;" : "=l"(ud) : "l"(ua), "l"(ub), "l"(uc));
    return reinterpret_cast<float2&>(ud);
}
__device__ __forceinline__ uint32_t smem_u32(const void* p){
    return (uint32_t)__cvta_generic_to_shared(p);
}
__device__ __forceinline__ void ldsm_x4(unsigned* r, uint32_t addr){
    asm volatile("ldmatrix.sync.aligned.m8n8.x4.shared.b16 {%0,%1,%2,%3}, [%4];\n"
        : "=r"(r[0]), "=r"(r[1]), "=r"(r[2]), "=r"(r[3]) : "r"(addr));
}
__device__ __forceinline__ void mma16816(float* c, const unsigned* a, const unsigned* b){
    asm volatile("mma.sync.aligned.m16n8k16.row.col.f32.bf16.bf16.f32 "
        "{%0,%1,%2,%3}, {%4,%5,%6,%7}, {%8,%9}, {%0,%1,%2,%3};\n"
        : "+f"(c[0]), "+f"(c[1]), "+f"(c[2]), "+f"(c[3])
        : "r"(a[0]), "r"(a[1]), "r"(a[2]), "r"(a[3]), "r"(b[0]), "r"(b[1]));
}
__device__ __forceinline__ unsigned ld_acq(const unsigned* p){
    unsigned v;
    asm volatile("ld.acquire.gpu.u32 %0, [%1];" : "=r"(v) : "l"(p) : "memory");
    return v;
}
__device__ __forceinline__ void red_release(unsigned* p){
    asm volatile("red.release.gpu.global.add.u32 [%0], %1;" :: "l"(p), "r"(1u) : "memory");
}
__device__ __forceinline__ void cp16(uint32_t dst, const void* src){
    asm volatile("cp.async.cg.shared.global [%0], [%1], 16;" :: "r"(dst), "l"(src) : "memory");
}
#define CP_COMMIT() asm volatile("cp.async.commit_group;" ::: "memory")
#define CP_WAIT1()  asm volatile("cp.async.wait_group 1;" ::: "memory")
#define CP_WAIT0()  asm volatile("cp.async.wait_group 0;" ::: "memory")
#define CLUSTER_ARRIVE() asm volatile("barrier.cluster.arrive.aligned;" ::: "memory")
#define CLUSTER_WAIT()   asm volatile("barrier.cluster.wait.aligned;" ::: "memory")

// ---------------- SMEM layout (dynamic, gru kernels) ----------------
#define GRU_BSH 0u
#define GRU_BSL 50688u
#define GRU_ASH 101376u
#define GRU_ASL 121856u
#define GRU_CS  142336u
#define GRU_DYN 207872u
#define SM_B_STRIDE 264
#define STL_BH  GRU_CS
#define STL_BL  (GRU_CS + 15360u)
// big-GEMM kernel layout
#define BIG_ASH 0u
#define BIG_ASL 20480u
#define BIG_BSH 40960u
#define BIG_BSL 56320u
#define BIG_DYN 71680u

// ---------------- sort rows by flen (descending, deterministic) ----------------
__global__ void rank_kernel(const int* __restrict__ flen){
    __shared__ int fl_s[NSEQ];
    for (int i = threadIdx.x; i < NSEQ; i += 256) fl_s[i] = flen[i];
    __syncthreads();
    const int i = blockIdx.x*256 + threadIdx.x;
    const int f = fl_s[i];
    int r = 0;
    for (int jj = 0; jj < NSEQ; ++jj) {
        int fj = fl_s[jj];
        r += (fj > f) || (fj == f && jj < i);
    }
    g_perm[r] = i;
    if ((r & 127) == 0) g_gmax[r >> 7] = f;
    if (blockIdx.x == 0 && threadIdx.x < 16) g_cnt[threadIdx.x] = 0u;
    if (i < 16*LSEQ) { g_c0[i] = 0u; g_c1[i] = 0u; }
    if (i == 0) { g_q0 = 0u; g_q1 = 0u; }
}

// ---------------- staging (cp.async) ----------------
__device__ __forceinline__ void stageA_seq(uint32_t sA_h, uint32_t sA_l,
        const __nv_bfloat16* __restrict__ Ah, const __nv_bfloat16* __restrict__ Al,
        const int* __restrict__ perm_s, int t, int kk, int tid){
    #pragma unroll
    for (int q = 0; q < 2; ++q) {
        int idx = q*256 + tid;
        int r = idx >> 2, ks = (idx & 3) << 3;
        size_t s = ((size_t)perm_s[r]*LSEQ + t)*HD + kk + ks;
        uint32_t d = (uint32_t)(r*40 + ks)*2u;
        cp16(sA_h + d, Ah + s);
        cp16(sA_l + d, Al + s);
    }
}
__device__ __forceinline__ void stageA_row(uint32_t sA_h, uint32_t sA_l,
        const __nv_bfloat16* __restrict__ Ah, const __nv_bfloat16* __restrict__ Al,
        const int* __restrict__ perm_s, int kk, int tid){
    #pragma unroll
    for (int q = 0; q < 2; ++q) {
        int idx = q*256 + tid;
        int r = idx >> 2, ks = (idx & 3) << 3;
        size_t s = (size_t)perm_s[r]*HD + kk + ks;
        uint32_t d = (uint32_t)(r*40 + ks)*2u;
        cp16(sA_h + d, Ah + s);
        cp16(sA_l + d, Al + s);
    }
}
__device__ __forceinline__ void stageB_cp(uint32_t sB_h, uint32_t sB_l,
        const __nv_bfloat16* __restrict__ Bh, const __nv_bfloat16* __restrict__ Bl,
        int ubu, int kk, int tid){
    #pragma unroll
    for (int q = 0; q < 2; ++q) {
        int idx = q*256 + tid;
        if (idx < 384) {
            int p = idx >> 2, ks = (idx & 3) << 3;
            int w = (p >> 5)*HD + ubu + (p & 31);
            size_t s = (size_t)w*HD + kk + ks;
            uint32_t d = (uint32_t)(p*40 + ks)*2u;
            cp16(sB_h + d, Bh + s);
            cp16(sB_l + d, Bl + s);
        }
    }
}
__device__ __forceinline__ void stageGI_piece(uint32_t cs, const float* __restrict__ GI,
        const int* __restrict__ perm_s, int t, size_t colbase, int piece, int tid){
    #pragma unroll
    for (int q = 0; q < 2; ++q) {
        int i = q*256 + tid;
        if (i < 384) {
            int i2 = piece*384 + i;
            int rl = i2 / 24, c16 = i2 % 24;
            const float* src = GI + ((size_t)perm_s[rl]*LSEQ + t)*G3 + colbase + c16*4;
            cp16(cs + (uint32_t)(rl*128 + c16*4)*4u, src);
        }
    }
}

// ---------------- MMA on one staged 32-k chunk (3-term hi/lo) ----------------
__device__ __forceinline__ void mma_chunk(
    float (&c)[2][6][4],
    uint32_t aAsh, uint32_t aAsl, uint32_t aBsh, uint32_t aBsl,
    int a_m, int a_k, int b_n, int b_k, int wm, int wn, int bstride, int bkoff)
{
    #pragma unroll
    for (int kt = 0; kt < 2; ++kt) {
        unsigned ah[2][4], al[2][4], bh[3][4], bl[3][4];
        #pragma unroll
        for (int mt = 0; mt < 2; ++mt) {
            uint32_t off = 2u*((wm*32 + mt*16 + a_m)*40 + kt*16 + a_k);
            ldsm_x4(ah[mt], aAsh + off);
            ldsm_x4(al[mt], aAsl + off);
        }
        #pragma unroll
        for (int np = 0; np < 3; ++np) {
            uint32_t off = 2u*((wn*48 + np*16 + b_n)*bstride + bkoff + kt*16 + b_k);
            ldsm_x4(bh[np], aBsh + off);
            ldsm_x4(bl[np], aBsl + off);
        }
        #pragma unroll
        for (int mt = 0; mt < 2; ++mt)
            #pragma unroll
            for (int nt = 0; nt < 6; ++nt) {
                const unsigned* B1 = &bh[nt>>1][(nt&1)*2];
                const unsigned* B2 = &bl[nt>>1][(nt&1)*2];
                mma16816(c[mt][nt], ah[mt], B1);
                mma16816(c[mt][nt], al[mt], B1);
                mma16816(c[mt][nt], ah[mt], B2);
            }
    }
}

// ---------------- hi/lo split conversions ----------------
__global__ void split_kernel(const float* __restrict__ x,
                             __nv_bfloat16* __restrict__ hi,
                             __nv_bfloat16* __restrict__ lo, int n){
    int i = blockIdx.x*256 + threadIdx.x;
    if (i < n){
        float v = x[i];
        __nv_bfloat16 h = __float2bfloat16(v);
        hi[i] = h;
        lo[i] = __float2bfloat16(v - __bfloat162float(h));
    }
}
__global__ void split_fx(const float* __restrict__ x,
                         __nv_bfloat16* __restrict__ hi,
                         __nv_bfloat16* __restrict__ lo,
                         const int* __restrict__ flen){
    int i = blockIdx.x*256 + threadIdx.x;
    int t   = (i >> 8) % LSEQ;
    int row = i / (LSEQ*HD);
    if (t >= flen[row]) return;
    float v = x[i];
    __nv_bfloat16 h = __float2bfloat16(v);
    hi[i] = h;
    lo[i] = __float2bfloat16(v - __bfloat162float(h));
}

// =====================================================================
// Claim-based big x-GEMM (layer 0): each CTA claims one queue index,
// computes that tile, releases g_c0[sg*LSEQ+t]. grid = NT_Q, 2 CTAs/SM.
// Exactly-once sharing with gru0's steal-fallback via the same queue.
// =====================================================================
__global__ __launch_bounds__(256, 2) void hmma_big(
    const __nv_bfloat16* __restrict__ Ah, const __nv_bfloat16* __restrict__ Al,
    const __nv_bfloat16* __restrict__ Bh, const __nv_bfloat16* __restrict__ Bl,
    float* __restrict__ GI, unsigned* __restrict__ relcnt)
{
    extern __shared__ char smraw[];
    __shared__ int perm_s[128];
    __shared__ unsigned widx_s;
    const uint32_t sb = smem_u32(smraw);
    const int tid  = threadIdx.x;
    const int lane = tid & 31, warp = tid >> 5;
    const int wm = warp >> 1, wn = warp & 1;

    if (tid == 0) widx_s = atomicAdd(&g_q0, 1u);
    __syncthreads();
    const unsigned widx = widx_s;
    if (widx >= (unsigned)NT_Q) return;
    const int t   = (int)(widx / 128u);
    const int sg  = (int)((widx / 8u) % 16u);
    const int ubu = (int)(widx % 8u) * 32;
    if (t >= g_gmax[sg]) return;

    if (tid < 128) perm_s[tid] = g_perm[sg*128 + tid];
    __syncthreads();

    const int grp = lane >> 3, rr = lane & 7;
    const int a_m = (grp & 1)*8 + rr, a_k = (grp >> 1)*8;
    const int b_n = (grp >> 1)*8 + rr, b_k = (grp & 1)*8;

    float c[2][6][4];
    #pragma unroll
    for (int mt = 0; mt < 2; ++mt)
        #pragma unroll
        for (int nt = 0; nt < 6; ++nt)
            #pragma unroll
            for (int q = 0; q < 4; ++q) c[mt][nt][q] = 0.f;

    stageA_seq(sb + BIG_ASH, sb + BIG_ASL, Ah, Al, perm_s, t, 0, tid);
    stageB_cp(sb + BIG_BSH, sb + BIG_BSL, Bh, Bl, ubu, 0, tid);
    CP_COMMIT();

    for (int kc = 0; kc < 8; ++kc) {
        const int buf = kc & 1;
        if (kc < 7) {
            const int nb = buf ^ 1;
            stageA_seq(sb + BIG_ASH + nb*10240u, sb + BIG_ASL + nb*10240u,
                       Ah, Al, perm_s, t, (kc+1)*32, tid);
            stageB_cp(sb + BIG_BSH + nb*7680u, sb + BIG_BSL + nb*7680u,
                      Bh, Bl, ubu, (kc+1)*32, tid);
            CP_COMMIT();
            CP_WAIT1();
        } else {
            CP_WAIT0();
        }
        __syncthreads();
        mma_chunk(c, sb + BIG_ASH + buf*10240u, sb + BIG_ASL + buf*10240u,
                     sb + BIG_BSH + buf*7680u,  sb + BIG_BSL + buf*7680u,
                  a_m, a_k, b_n, b_k, wm, wn, 40, 0);
        __syncthreads();
    }

    const size_t colbase = (size_t)(ubu >> 5) * 96;
    #pragma unroll
    for (int mt = 0; mt < 2; ++mt)
        #pragma unroll
        for (int nt = 0; nt < 6; ++nt) {
            int rl = wm*32 + mt*16 + (lane >> 2);
            int cl = wn*48 + nt*8 + ((lane & 3) << 1);
            size_t r0 = ((size_t)perm_s[rl]*LSEQ + t)*G3;
            size_t r1 = ((size_t)perm_s[rl+8]*LSEQ + t)*G3;
            *(float2*)&GI[r0 + colbase + cl] = make_float2(c[mt][nt][0], c[mt][nt][1]);
            *(float2*)&GI[r1 + colbase + cl] = make_float2(c[mt][nt][2], c[mt][nt][3]);
        }

    __threadfence();
    __syncthreads();
    if (tid == 0) red_release(&relcnt[sg*LSEQ + t]);
}

// =====================================================================
// Steal one x-GEMM tile inside the gru kernel (GRU smem layout).
// =====================================================================
__device__ __noinline__ void do_tile(unsigned widx, uint32_t sb,
    const __nv_bfloat16* __restrict__ Axh, const __nv_bfloat16* __restrict__ Axl,
    const __nv_bfloat16* __restrict__ Bwh, const __nv_bfloat16* __restrict__ Bwl,
    float* __restrict__ GIout, unsigned* relcnt, const unsigned* gate,
    int* perm2_s)
{
    const int tid = threadIdx.x;
    const int lane = tid & 31, warp = tid >> 5;
    const int wm = warp >> 1, wn = warp & 1;
    const int t   = (int)(widx / 128u);
    const int sg  = (int)((widx / 8u) % 16u);
    const int ubx = (int)(widx % 8u);
    if (t >= g_gmax[sg]) return;

    if (gate && tid == 0) {
        const unsigned tgt = 8u*(unsigned)(t+1);
        while (ld_acq(&gate[sg]) < tgt) __nanosleep(64);
    }
    if (tid < 128) perm2_s[tid] = g_perm[sg*128 + tid];
    __syncthreads();

    const int grp = lane >> 3, rr = lane & 7;
    const int a_m = (grp & 1)*8 + rr, a_k = (grp >> 1)*8;
    const int b_n = (grp >> 1)*8 + rr, b_k = (grp & 1)*8;

    float c[2][6][4];
    #pragma unroll
    for (int mt = 0; mt < 2; ++mt)
        #pragma unroll
        for (int nt = 0; nt < 6; ++nt)
            #pragma unroll
            for (int q = 0; q < 4; ++q) c[mt][nt][q] = 0.f;

    stageA_seq(sb + GRU_ASH, sb + GRU_ASL, Axh, Axl, perm2_s, t, 0, tid);
    stageB_cp(sb + STL_BH, sb + STL_BL, Bwh, Bwl, ubx*32, 0, tid);
    CP_COMMIT();

    for (int kc = 0; kc < 8; ++kc) {
        const int buf = kc & 1;
        if (kc < 7) {
            const int nb = buf ^ 1;
            stageA_seq(sb + GRU_ASH + nb*10240u, sb + GRU_ASL + nb*10240u,
                       Axh, Axl, perm2_s, t, (kc+1)*32, tid);
            stageB_cp(sb + STL_BH + nb*7680u, sb + STL_BL + nb*7680u,
                      Bwh, Bwl, ubx*32, (kc+1)*32, tid);
            CP_COMMIT();
            CP_WAIT1();
        } else {
            CP_WAIT0();
        }
        __syncthreads();
        mma_chunk(c, sb + GRU_ASH + buf*10240u, sb + GRU_ASL + buf*10240u,
                     sb + STL_BH + buf*7680u,  sb + STL_BL + buf*7680u,
                  a_m, a_k, b_n, b_k, wm, wn, 40, 0);
        __syncthreads();
    }

    const size_t cb = (size_t)ubx * 96;
    #pragma unroll
    for (int mt = 0; mt < 2; ++mt)
        #pragma unroll
        for (int nt = 0; nt < 6; ++nt) {
            int rl = wm*32 + mt*16 + (lane >> 2);
            int cl = wn*48 + nt*8 + ((lane & 3) << 1);
            size_t r0 = ((size_t)perm2_s[rl]*LSEQ + t)*G3;
            size_t r1 = ((size_t)perm2_s[rl+8]*LSEQ + t)*G3;
            *(float2*)&GIout[r0 + cb + cl] = make_float2(c[mt][nt][0], c[mt][nt][1]);
            *(float2*)&GIout[r1 + cb + cl] = make_float2(c[mt][nt][2], c[mt][nt][3]);
        }

    __threadfence();
    __syncthreads();
    if (tid == 0) red_release(&relcnt[sg*LSEQ + t]);
}

// =====================================================================
// Persistent GRU recurrence. Cluster (1,8) = one rowgroup (8 unit-CTAs).
// LAYER 0: per-step GI gate with steal-fallback from q0; releases g_cnt;
//          post-rec drains q0 then q1 (L1 tiles gated on g_cnt).
// LAYER 1: GI2 fully ready; pure recurrence with cluster barriers.
// =====================================================================
template<int LAYER>
__global__ void __cluster_dims__(1, 8, 1) __launch_bounds__(256) gru_persist(
    const int* __restrict__ flen,
    const float* __restrict__ bih, const float* __restrict__ bhh)
{
    extern __shared__ char smraw[];
    __shared__ int perm_s[128];
    __shared__ int flen_s[128];
    __shared__ int perm2_s[128];
    __shared__ unsigned act_s;
    const uint32_t sb = smem_u32(smraw);
    unsigned short* Bsh = (unsigned short*)(smraw + GRU_BSH);
    unsigned short* Bsl = (unsigned short*)(smraw + GRU_BSL);
    float* Cs = (float*)(smraw + GRU_CS);
    const uint32_t csb = sb + GRU_CS;

    const int tid  = threadIdx.x;
    const int lane = tid & 31, warp = tid >> 5;
    const int wm = warp >> 1, wn = warp & 1;
    const int rg   = blockIdx.x;
    const int ubu  = blockIdx.y * 32;
    const int tmax = g_gmax[rg];

    if (tid < 128) {
        int p = g_perm[rg*128 + tid];
        perm_s[tid] = p;
        flen_s[tid] = flen[p];
    }

    const __nv_bfloat16* Whh_h = g_Wh[LAYER ? 3 : 1];
    const __nv_bfloat16* Whh_l = g_Wl[LAYER ? 3 : 1];
    const float* GIl = LAYER ? g_GI2 : g_GI;

    // ---- load Whh tile (resident for all steps) ----
    for (int idx = tid; idx < 96*32; idx += 256) {
        int p = idx >> 5, ks = (idx & 31) << 3;
        int w = (p >> 5)*HD + ubu + (p & 31);
        *(uint4*)&Bsh[p*SM_B_STRIDE + ks] = *(const uint4*)&Whh_h[(size_t)w*HD + ks];
        *(uint4*)&Bsl[p*SM_B_STRIDE + ks] = *(const uint4*)&Whh_l[(size_t)w*HD + ks];
    }
    __syncthreads();

    const int grp = lane >> 3, rr = lane & 7;
    const int a_m = (grp & 1)*8 + rr, a_k = (grp >> 1)*8;
    const int b_n = (grp >> 1)*8 + rr, b_k = (grp & 1)*8;

    const int jl = tid & 31;
    const int j  = ubu + jl;
    const float b_r  = bih[j]      + bhh[j];
    const float b_z  = bih[HD+j]   + bhh[HD+j];
    const float bi_n = bih[2*HD+j];
    const float bh_n = bhh[2*HD+j];
    const size_t colbase = (size_t)blockIdx.y * 96;

    for (int t = 0; t < tmax; ++t) {
        if (LAYER == 0) {
            // ---- wait for GI(rg,t); steal L0 tiles while not ready ----
            unsigned* myCnt = &g_c0[rg*LSEQ + t];
            for (;;) {
                __syncthreads();
                if (tid == 0) {
                    if (ld_acq(myCnt) >= 8u) act_s = 0u;
                    else {
                        unsigned w = atomicAdd(&g_q0, 1u);
                        act_s = (w < (unsigned)NT_Q) ? (w + 2u) : 1u;
                    }
                }
                __syncthreads();
                const unsigned a = act_s;
                if (a == 0u) break;
                if (a == 1u) {
                    if (tid == 0) { while (ld_acq(myCnt) < 8u) __nanosleep(64); }
                    __syncthreads();
                    break;
                }
                do_tile(a - 2u, sb, g_FXh, g_FXl, g_Wh[0], g_Wl[0],
                        g_GI, g_c0, nullptr, perm2_s);
            }
        }

        const int pa = t & 1, pb = (t+1) & 1;
        const __nv_bfloat16* Ahp = g_Hh[pa];
        const __nv_bfloat16* Alp = g_Hl[pa];
        __nv_bfloat16* Hnh = g_Hh[pb];
        __nv_bfloat16* Hnl = g_Hl[pb];

        float c[2][6][4];
        #pragma unroll
        for (int mt = 0; mt < 2; ++mt)
            #pragma unroll
            for (int nt = 0; nt < 6; ++nt)
                #pragma unroll
                for (int q = 0; q < 4; ++q) c[mt][nt][q] = 0.f;

        if (t > 0) {
            stageA_row(sb + GRU_ASH, sb + GRU_ASL, Ahp, Alp, perm_s, 0, tid);
            stageGI_piece(csb, GIl, perm_s, t, colbase, 0, tid);
            CP_COMMIT();
            for (int kc = 0; kc < 8; ++kc) {
                const int buf = kc & 1;
                if (kc < 7) {
                    const int nb = buf ^ 1;
                    stageA_row(sb + GRU_ASH + nb*10240u, sb + GRU_ASL + nb*10240u,
                               Ahp, Alp, perm_s, (kc+1)*32, tid);
                    stageGI_piece(csb, GIl, perm_s, t, colbase, kc+1, tid);
                    CP_COMMIT();
                    CP_WAIT1();
                } else {
                    CP_WAIT0();
                }
                __syncthreads();
                mma_chunk(c, sb + GRU_ASH + buf*10240u, sb + GRU_ASL + buf*10240u,
                             sb + GRU_BSH, sb + GRU_BSL,
                          a_m, a_k, b_n, b_k, wm, wn, SM_B_STRIDE, kc*32);
                __syncthreads();
            }
        } else {
            #pragma unroll
            for (int pc = 0; pc < 8; ++pc)
                stageGI_piece(csb, GIl, perm_s, t, colbase, pc, tid);
            CP_COMMIT();
            CP_WAIT0();
            __syncthreads();
        }

        // ---- merge fragments: r/z add into Cs, n store to hh_n column ----
        #pragma unroll
        for (int mt = 0; mt < 2; ++mt)
            #pragma unroll
            for (int nt = 0; nt < 6; ++nt) {
                int rl = wm*32 + mt*16 + (lane >> 2);
                int cl = wn*48 + nt*8 + ((lane & 3) << 1);
                const bool is_n = (cl >= 64);
                const int ccl = is_n ? cl + 32 : cl;
                float2* p0 = (float2*)&Cs[rl*128 + ccl];
                float2* p1 = (float2*)&Cs[(rl+8)*128 + ccl];
                if (is_n) {
                    *p0 = make_float2(c[mt][nt][0], c[mt][nt][1]);
                    *p1 = make_float2(c[mt][nt][2], c[mt][nt][3]);
                } else {
                    float2 v0 = *p0, v1 = *p1;
                    *p0 = make_float2(v0.x + c[mt][nt][0], v0.y + c[mt][nt][1]);
                    *p1 = make_float2(v1.x + c[mt][nt][2], v1.y + c[mt][nt][3]);
                }
            }
        __syncthreads();

        // ---- gate epilogue ----
        #pragma unroll
        for (int i = 0; i < 16; ++i) {
            const int rl  = (tid >> 5) + i*8;
            const int row = perm_s[rl];
            const float r = fast_sigmoid(Cs[rl*128 + jl]      + b_r);
            const float z = fast_sigmoid(Cs[rl*128 + 32 + jl] + b_z);
            const float n = fast_tanh(Cs[rl*128 + 64 + jl] + bi_n +
                                      r*(Cs[rl*128 + 96 + jl] + bh_n));
            float hp = 0.f;
            if (t > 0)
                hp = __bfloat162float(Ahp[(size_t)row*HD + j]) +
                     __bfloat162float(Alp[(size_t)row*HD + j]);
            const float h  = (1.f - z)*n + z*hp;
            __nv_bfloat16 hh = __float2bfloat16(h);
            __nv_bfloat16 hl = __float2bfloat16(h - __bfloat162float(hh));
            Hnh[(size_t)row*HD + j] = hh;
            Hnl[(size_t)row*HD + j] = hl;
            if (LAYER == 0) {
                if (t < flen_s[rl]) {           // dead X1 slots stay zero
                    size_t xi = ((size_t)row*LSEQ + t)*HD + j;
                    g_X1h[xi] = hh; g_X1l[xi] = hl;
                }
            } else {
                if (t == flen_s[rl] - 1) g_FL[(size_t)row*HD + j] = h;
            }
        }

        // ---- step barrier: release for external stealers, cluster-sync ----
        __threadfence();
        __syncthreads();
        if (LAYER == 0 && tid == 0) red_release(&g_cnt[rg]);
        CLUSTER_ARRIVE();
        CLUSTER_WAIT();
    }

    if (LAYER == 0) {
        // ---- drain remaining L0 tiles, then all L1 tiles ----
        for (;;) {
            __syncthreads();
            if (tid == 0) {
                unsigned w = atomicAdd(&g_q0, 1u);
                act_s = (w < (unsigned)NT_Q) ? (w + 2u) : 1u;
            }
            __syncthreads();
            const unsigned a = act_s;
            if (a == 1u) break;
            do_tile(a - 2u, sb, g_FXh, g_FXl, g_Wh[0], g_Wl[0], g_GI, g_c0,
                    nullptr, perm2_s);
        }
        for (;;) {
            __syncthreads();
            if (tid == 0) {
                unsigned w = atomicAdd(&g_q1, 1u);
                act_s = (w < (unsigned)NT_Q) ? (w + 2u) : 1u;
            }
            __syncthreads();
            const unsigned a = act_s;
            if (a == 1u) break;
            do_tile(a - 2u, sb, g_X1h, g_X1l, g_Wh[2], g_Wl[2], g_GI2, g_c1,
                    g_cnt, perm2_s);
        }
    }
}

// ---------------- fp32 tail GEMM (small) ----------------
template<int TRANSW>
__global__ __launch_bounds__(256) void sgemm_tn(
    const float* __restrict__ A, const float* __restrict__ W, float* __restrict__ C,
    int M, int N, int K)
{
    __shared__ float As[32][68];
    __shared__ float Bs[32][68];
    const int tid = threadIdx.x;
    const int tx = tid & 15, ty = tid >> 4;
    const int mb = blockIdx.x * 64, nb = blockIdx.y * 64;

    float2 acc[4][2];
    #pragma unroll
    for (int i = 0; i < 4; ++i) { acc[i][0] = make_float2(0.f,0.f); acc[i][1] = make_float2(0.f,0.f); }

    for (int kc = 0; kc < K; kc += 32) {
        #pragma unroll
        for (int q = 0; q < 2; ++q) {
            int idx = q*256 + tid;
            int row = idx >> 3;
            int k4  = (idx & 7) << 2;
            const float4 v = *reinterpret_cast<const float4*>(&A[(size_t)(mb+row)*K + kc + k4]);
            As[k4+0][row] = v.x; As[k4+1][row] = v.y; As[k4+2][row] = v.z; As[k4+3][row] = v.w;
        }
        if (!TRANSW) {
            #pragma unroll
            for (int q = 0; q < 2; ++q) {
                int idx = q*256 + tid;
                int n  = idx >> 3;
                int k4 = (idx & 7) << 2;
                const float4 v = *reinterpret_cast<const float4*>(&W[(size_t)(nb+n)*K + kc + k4]);
                Bs[k4+0][n] = v.x; Bs[k4+1][n] = v.y; Bs[k4+2][n] = v.z; Bs[k4+3][n] = v.w;
            }
        } else {
            #pragma unroll
            for (int q = 0; q < 2; ++q) {
                int idx = q*256 + tid;
                int k  = idx >> 4;
                int n4 = (idx & 15) << 2;
                const float4 v = *reinterpret_cast<const float4*>(&W[(size_t)(kc+k)*N + nb + n4]);
                *reinterpret_cast<float4*>(&Bs[k][n4]) = v;
            }
        }
        __syncthreads();
        #pragma unroll
        for (int k = 0; k < 32; ++k) {
            const float4 a4 = *reinterpret_cast<const float4*>(&As[k][ty<<2]);
            const float4 b4 = *reinterpret_cast<const float4*>(&Bs[k][tx<<2]);
            const float2 b0 = make_float2(b4.x, b4.y);
            const float2 b1 = make_float2(b4.z, b4.w);
            float av[4] = {a4.x, a4.y, a4.z, a4.w};
            #pragma unroll
            for (int i = 0; i < 4; ++i) {
                float2 aa = make_float2(av[i], av[i]);
                acc[i][0] = ffma2(aa, b0, acc[i][0]);
                acc[i][1] = ffma2(aa, b1, acc[i][1]);
            }
        }
        __syncthreads();
    }
    #pragma unroll
    for (int i = 0; i < 4; ++i) {
        const int row = mb + (ty<<2) + i;
        float4 o;
        o.x = acc[i][0].x; o.y = acc[i][0].y; o.z = acc[i][1].x; o.w = acc[i][1].y;
        *reinterpret_cast<float4*>(&C[(size_t)row*N + nb + (tx<<2)]) = o;
    }
}

__global__ void build_cat(const float* __restrict__ self_x,
                          const float* __restrict__ FL,
                          float* __restrict__ CAT){
    const int m = blockIdx.x, tid = threadIdx.x;
    CAT[(size_t)m*2*HD + tid]      = self_x[(size_t)(m>>5)*HD + tid];
    CAT[(size_t)m*2*HD + HD + tid] = FL[(size_t)m*HD + tid];
}

__global__ __launch_bounds__(256) void tf_kernel(
    const float* __restrict__ common_x, const float* __restrict__ common_time,
    const float* __restrict__ V, const int* __restrict__ clen, float* __restrict__ TF)
{
    const int m = blockIdx.x;
    __shared__ float vs[HD];
    __shared__ float wsum[8];
    const int tid = threadIdx.x;
    vs[tid] = V[(size_t)m*HD + tid];
    __syncthreads();
    const int warp = tid >> 5, lane = tid & 31;
    const int cl = clen[m];
    float acc = 0.f;
    for (int s = warp; s < cl; s += 8) {
        const float* cx = common_x + ((size_t)m*SSEQ + s)*HD;
        float p = 0.f;
        #pragma unroll
        for (int q = 0; q < 8; ++q) p += cx[lane + 32*q] * vs[lane + 32*q];
        #pragma unroll
        for (int off = 16; off; off >>= 1) p += __shfl_xor_sync(0xffffffffu, p, off);
        if (lane == 0)
            acc += softplus_f(p) * expf(-common_time[(size_t)m*SSEQ + s]);
    }
    if (lane == 0) wsum[warp] = acc;
    __syncthreads();
    if (tid == 0) {
        float s = 0.f;
        for (int w = 0; w < 8; ++w) s += wsum[w];
        TF[m] = s;
    }
}

__global__ __launch_bounds__(256) void out_kernel(
    const float* __restrict__ TF, const float* __restrict__ FL,
    const int* __restrict__ fnum, float* __restrict__ out)
{
    const int b = blockIdx.x;
    __shared__ float w[MAXF];
    const int tid = threadIdx.x;
    const int fn = fnum[b];
    if (tid < MAXF) w[tid] = (tid < fn) ? TF[b*MAXF + tid] : 0.f;
    __syncthreads();
    if (tid == 0) {
        float mx = w[0];
        for (int f = 1; f < MAXF; ++f) mx = fmaxf(mx, w[f]);
        float s = 0.f;
        for (int f = 0; f < MAXF; ++f) { float e = expf(w[f] - mx); w[f] = e; s += e; }
        float inv = 1.f / s;
        for (int f = 0; f < MAXF; ++f) w[f] *= inv;
    }
    __syncthreads();
    float acc = 0.f;
    for (int f = 0; f < fn; ++f)
        acc += w[f] * FL[(size_t)(b*MAXF + f)*HD + tid];
    out[(size_t)b*HD + tid] = acc;
}

// ---------------- host launcher ----------------
extern "C" void kernel_launch(void* const* d_in, const int* in_sizes, int n_in,
                              void* d_out, int out_size)
{
    const float* self_x      = (const float*)d_in[0];
    const float* common_x    = (const float*)d_in[1];
    const float* common_time = (const float*)d_in[2];
    const float* friend_x    = (const float*)d_in[3];
    const float* Wih0 = (const float*)d_in[4];
    const float* Whh0 = (const float*)d_in[5];
    const float* bih0 = (const float*)d_in[6];
    const float* bhh0 = (const float*)d_in[7];
    const float* Wih1 = (const float*)d_in[8];
    const float* Whh1 = (const float*)d_in[9];
    const float* bih1 = (const float*)d_in[10];
    const float* bhh1 = (const float*)d_in[11];
    const float* Wf   = (const float*)d_in[12];
    const float* Wb   = (const float*)d_in[13];
    const int*   flen = (const int*)d_in[14];
    const int*   fnum = (const int*)d_in[15];
    const int*   clen = (const int*)d_in[16];
    float* out = (float*)d_out;

    float *GI, *FL, *CAT, *SF, *V, *TF;
    __nv_bfloat16 *FXh, *FXl, *Wh, *Wl;
    unsigned *c0;
    cudaGetSymbolAddress((void**)&GI,  g_GI);
    cudaGetSymbolAddress((void**)&FXh, g_FXh);
    cudaGetSymbolAddress((void**)&FXl, g_FXl);
    cudaGetSymbolAddress((void**)&Wh,  g_Wh);
    cudaGetSymbolAddress((void**)&Wl,  g_Wl);
    cudaGetSymbolAddress((void**)&FL,  g_FL);
    cudaGetSymbolAddress((void**)&CAT, g_CAT);
    cudaGetSymbolAddress((void**)&SF,  g_SF);
    cudaGetSymbolAddress((void**)&V,   g_V);
    cudaGetSymbolAddress((void**)&TF,  g_TF);
    cudaGetSymbolAddress((void**)&c0,  g_c0);

    const float* Wsrc[4] = {Wih0, Whh0, Wih1, Whh1};

    static bool init_done = false;
    static cudaStream_t sB;
    static cudaEvent_t evA, evB;
    if (!init_done) {
        cudaFuncSetAttribute(hmma_big,       cudaFuncAttributeMaxDynamicSharedMemorySize, BIG_DYN);
        cudaFuncSetAttribute(gru_persist<0>, cudaFuncAttributeMaxDynamicSharedMemorySize, GRU_DYN);
        cudaFuncSetAttribute(gru_persist<1>, cudaFuncAttributeMaxDynamicSharedMemorySize, GRU_DYN);
        cudaStreamCreateWithFlags(&sB, cudaStreamNonBlocking);
        cudaEventCreateWithFlags(&evA, cudaEventDisableTiming);
        cudaEventCreateWithFlags(&evB, cudaEventDisableTiming);
        init_done = true;
    }

    // --- sort rows by flen + reset counters/queues ---
    rank_kernel<<<NSEQ/256, 256>>>(flen);

    // --- conversions ---
    split_fx<<<((size_t)MTOT*HD + 255)/256, 256>>>(friend_x, FXh, FXl, flen);
    for (int w = 0; w < 4; ++w)
        split_kernel<<<(G3*HD + 255)/256, 256>>>(Wsrc[w], Wh + (size_t)w*G3*HD,
                                                 Wl + (size_t)w*G3*HD, G3*HD);
    cudaEventRecord(evA, 0);

    // ---- L0 big GEMM (claim-based) on main stream ----
    hmma_big<<<NT_Q, 256, BIG_DYN>>>(FXh, FXl,
        Wh + 0*(size_t)G3*HD, Wl + 0*(size_t)G3*HD, GI, c0);

    // ---- gru0 (gated per-step on g_c0 + steal-fallback) on side stream ----
    cudaStreamWaitEvent(sB, evA, 0);
    gru_persist<0><<<dim3(16, 8), 256, GRU_DYN, sB>>>(flen, bih0, bhh0);
    // ---- gru1 after gru0 (all GI2 drained inside gru0) ----
    gru_persist<1><<<dim3(16, 8), 256, GRU_DYN, sB>>>(flen, bih1, bhh1);
    cudaEventRecord(evB, sB);
    cudaStreamWaitEvent(0, evB, 0);

    // ---- tail ----
    build_cat<<<NSEQ, 256>>>(self_x, FL, CAT);
    sgemm_tn<0><<<dim3(NSEQ/64, HD/64), 256>>>(CAT, Wf, SF, NSEQ, HD, 2*HD);
    sgemm_tn<1><<<dim3(NSEQ/64, HD/64), 256>>>(SF,  Wb, V,  NSEQ, HD, HD);
    tf_kernel<<<NSEQ, 256>>>(common_x, common_time, V, clen, TF);
    out_kernel<<<NBATCH, 256>>>(TF, FL, fnum, out);
}

// round 13
// speedup vs baseline: 1.0233x; 1.0233x over previous
#include <cuda_runtime.h>
#include <cuda_bf16.h>
#include <cstdint>
#include <math.h>

#define HD    256
#define LSEQ  50
#define SSEQ  50
#define NBATCH 64
#define MAXF  32
#define NSEQ  (NBATCH*MAXF)            // 2048
#define MTOT  (NSEQ*LSEQ)              // 102400
#define G3    (3*HD)                   // 768
#define NT_Q  (16*LSEQ*8)              // 6400 GEMM tiles (layer-1 queue)

// ---------------- device scratch ----------------
__device__ __nv_bfloat16  g_Hh[2][NSEQ*HD];
__device__ __nv_bfloat16  g_Hl[2][NSEQ*HD];
__device__ float          g_GI[(size_t)MTOT*G3];    // layer-0 pre-activations
__device__ float          g_GI2[(size_t)MTOT*G3];   // layer-1 pre-activations
__device__ __nv_bfloat16  g_FXh[(size_t)MTOT*HD];
__device__ __nv_bfloat16  g_FXl[(size_t)MTOT*HD];
__device__ __nv_bfloat16  g_X1h[(size_t)MTOT*HD];
__device__ __nv_bfloat16  g_X1l[(size_t)MTOT*HD];
__device__ __nv_bfloat16  g_Wh[4][G3*HD];           // Wih0,Whh0,Wih1,Whh1 (hi)
__device__ __nv_bfloat16  g_Wl[4][G3*HD];
__device__ float g_FL[NSEQ*HD];
__device__ float g_CAT[NSEQ*2*HD];
__device__ float g_SF[NSEQ*HD];
__device__ float g_V[NSEQ*HD];
__device__ float g_TF[NSEQ];
__device__ unsigned g_cnt[16];            // L0 rowgroup step counters (gate L1 tiles)
__device__ unsigned g_q1;                 // layer-1 GEMM tile queue
__device__ int g_perm[NSEQ];
__device__ int g_gmax[16];

// ---------------- helpers ----------------
__device__ __forceinline__ float fast_sigmoid(float x){
    return __fdividef(1.f, 1.f + __expf(-x));
}
__device__ __forceinline__ float fast_tanh(float x){
    return 1.f - __fdividef(2.f, __expf(2.f*x) + 1.f);
}
__device__ __forceinline__ float softplus_f(float x){
    return (x > 20.f) ? x : log1pf(expf(x));
}
__device__ __forceinline__ float2 ffma2(float2 a, float2 b, float2 c){
    unsigned long long ua = reinterpret_cast<unsigned long long&>(a);
    unsigned long long ub = reinterpret_cast<unsigned long long&>(b);
    unsigned long long uc = reinterpret_cast<unsigned long long&>(c);
    unsigned long long ud;
    asm("fma.rn.f32x2 %0, %1, %2, %3;" : "=l"(ud) : "l"(ua), "l"(ub), "l"(uc));
    return reinterpret_cast<float2&>(ud);
}
__device__ __forceinline__ uint32_t smem_u32(const void* p){
    return (uint32_t)__cvta_generic_to_shared(p);
}
__device__ __forceinline__ void ldsm_x4(unsigned* r, uint32_t addr){
    asm volatile("ldmatrix.sync.aligned.m8n8.x4.shared.b16 {%0,%1,%2,%3}, [%4];\n"
        : "=r"(r[0]), "=r"(r[1]), "=r"(r[2]), "=r"(r[3]) : "r"(addr));
}
__device__ __forceinline__ void mma16816(float* c, const unsigned* a, const unsigned* b){
    asm volatile("mma.sync.aligned.m16n8k16.row.col.f32.bf16.bf16.f32 "
        "{%0,%1,%2,%3}, {%4,%5,%6,%7}, {%8,%9}, {%0,%1,%2,%3};\n"
        : "+f"(c[0]), "+f"(c[1]), "+f"(c[2]), "+f"(c[3])
        : "r"(a[0]), "r"(a[1]), "r"(a[2]), "r"(a[3]), "r"(b[0]), "r"(b[1]));
}
__device__ __forceinline__ unsigned ld_acq(const unsigned* p){
    unsigned v;
    asm volatile("ld.acquire.gpu.u32 %0, [%1];" : "=r"(v) : "l"(p) : "memory");
    return v;
}
__device__ __forceinline__ void red_release(unsigned* p){
    asm volatile("red.release.gpu.global.add.u32 [%0], %1;" :: "l"(p), "r"(1u) : "memory");
}
__device__ __forceinline__ void cp16(uint32_t dst, const void* src){
    asm volatile("cp.async.cg.shared.global [%0], [%1], 16;" :: "r"(dst), "l"(src) : "memory");
}
#define CP_COMMIT() asm volatile("cp.async.commit_group;" ::: "memory")
#define CP_WAIT1()  asm volatile("cp.async.wait_group 1;" ::: "memory")
#define CP_WAIT0()  asm volatile("cp.async.wait_group 0;" ::: "memory")
#define CLUSTER_ARRIVE() asm volatile("barrier.cluster.arrive.aligned;" ::: "memory")
#define CLUSTER_WAIT()   asm volatile("barrier.cluster.wait.aligned;" ::: "memory")

// ---------------- SMEM layouts ----------------
#define GRU_BSH 0u
#define GRU_BSL 50688u
#define GRU_ASH 101376u
#define GRU_ASL 121856u
#define GRU_CS  142336u
#define GRU_DYN 207872u
#define SM_B_STRIDE 264
#define STL_BH  GRU_CS
#define STL_BL  (GRU_CS + 15360u)
// big-GEMM kernel
#define BIG_ASH 0u
#define BIG_ASL 20480u
#define BIG_BSH 40960u
#define BIG_BSL 56320u
#define BIG_DYN 71680u

// ---------------- sort rows by flen (descending, deterministic) ----------------
__global__ void rank_kernel(const int* __restrict__ flen){
    __shared__ int fl_s[NSEQ];
    for (int i = threadIdx.x; i < NSEQ; i += 256) fl_s[i] = flen[i];
    __syncthreads();
    const int i = blockIdx.x*256 + threadIdx.x;
    const int f = fl_s[i];
    int r = 0;
    for (int jj = 0; jj < NSEQ; ++jj) {
        int fj = fl_s[jj];
        r += (fj > f) || (fj == f && jj < i);
    }
    g_perm[r] = i;
    if ((r & 127) == 0) g_gmax[r >> 7] = f;
    if (blockIdx.x == 0 && threadIdx.x < 16) g_cnt[threadIdx.x] = 0u;
    if (i == 0) g_q1 = 0u;
}

// ---------------- staging (cp.async) ----------------
__device__ __forceinline__ void stageA_seq(uint32_t sA_h, uint32_t sA_l,
        const __nv_bfloat16* __restrict__ Ah, const __nv_bfloat16* __restrict__ Al,
        const int* __restrict__ perm_s, int t, int kk, int tid){
    #pragma unroll
    for (int q = 0; q < 2; ++q) {
        int idx = q*256 + tid;
        int r = idx >> 2, ks = (idx & 3) << 3;
        size_t s = ((size_t)perm_s[r]*LSEQ + t)*HD + kk + ks;
        uint32_t d = (uint32_t)(r*40 + ks)*2u;
        cp16(sA_h + d, Ah + s);
        cp16(sA_l + d, Al + s);
    }
}
__device__ __forceinline__ void stageA_row(uint32_t sA_h, uint32_t sA_l,
        const __nv_bfloat16* __restrict__ Ah, const __nv_bfloat16* __restrict__ Al,
        const int* __restrict__ perm_s, int kk, int tid){
    #pragma unroll
    for (int q = 0; q < 2; ++q) {
        int idx = q*256 + tid;
        int r = idx >> 2, ks = (idx & 3) << 3;
        size_t s = (size_t)perm_s[r]*HD + kk + ks;
        uint32_t d = (uint32_t)(r*40 + ks)*2u;
        cp16(sA_h + d, Ah + s);
        cp16(sA_l + d, Al + s);
    }
}
__device__ __forceinline__ void stageB_cp(uint32_t sB_h, uint32_t sB_l,
        const __nv_bfloat16* __restrict__ Bh, const __nv_bfloat16* __restrict__ Bl,
        int ubu, int kk, int tid){
    #pragma unroll
    for (int q = 0; q < 2; ++q) {
        int idx = q*256 + tid;
        if (idx < 384) {
            int p = idx >> 2, ks = (idx & 3) << 3;
            int w = (p >> 5)*HD + ubu + (p & 31);
            size_t s = (size_t)w*HD + kk + ks;
            uint32_t d = (uint32_t)(p*40 + ks)*2u;
            cp16(sB_h + d, Bh + s);
            cp16(sB_l + d, Bl + s);
        }
    }
}
__device__ __forceinline__ void stageGI_piece(uint32_t cs, const float* __restrict__ GI,
        const int* __restrict__ perm_s, int t, size_t colbase, int piece, int tid){
    #pragma unroll
    for (int q = 0; q < 2; ++q) {
        int i = q*256 + tid;
        if (i < 384) {
            int i2 = piece*384 + i;
            int rl = i2 / 24, c16 = i2 % 24;
            const float* src = GI + ((size_t)perm_s[rl]*LSEQ + t)*G3 + colbase + c16*4;
            cp16(cs + (uint32_t)(rl*128 + c16*4)*4u, src);
        }
    }
}

// ---------------- MMA on one staged 32-k chunk (3-term hi/lo) ----------------
__device__ __forceinline__ void mma_chunk(
    float (&c)[2][6][4],
    uint32_t aAsh, uint32_t aAsl, uint32_t aBsh, uint32_t aBsl,
    int a_m, int a_k, int b_n, int b_k, int wm, int wn, int bstride, int bkoff)
{
    #pragma unroll
    for (int kt = 0; kt < 2; ++kt) {
        unsigned ah[2][4], al[2][4], bh[3][4], bl[3][4];
        #pragma unroll
        for (int mt = 0; mt < 2; ++mt) {
            uint32_t off = 2u*((wm*32 + mt*16 + a_m)*40 + kt*16 + a_k);
            ldsm_x4(ah[mt], aAsh + off);
            ldsm_x4(al[mt], aAsl + off);
        }
        #pragma unroll
        for (int np = 0; np < 3; ++np) {
            uint32_t off = 2u*((wn*48 + np*16 + b_n)*bstride + bkoff + kt*16 + b_k);
            ldsm_x4(bh[np], aBsh + off);
            ldsm_x4(bl[np], aBsl + off);
        }
        #pragma unroll
        for (int mt = 0; mt < 2; ++mt)
            #pragma unroll
            for (int nt = 0; nt < 6; ++nt) {
                const unsigned* B1 = &bh[nt>>1][(nt&1)*2];
                const unsigned* B2 = &bl[nt>>1][(nt&1)*2];
                mma16816(c[mt][nt], ah[mt], B1);
                mma16816(c[mt][nt], al[mt], B1);
                mma16816(c[mt][nt], ah[mt], B2);
            }
    }
}

// ---------------- hi/lo split conversions ----------------
__global__ void split_kernel(const float* __restrict__ x,
                             __nv_bfloat16* __restrict__ hi,
                             __nv_bfloat16* __restrict__ lo, int n){
    int i = blockIdx.x*256 + threadIdx.x;
    if (i < n){
        float v = x[i];
        __nv_bfloat16 h = __float2bfloat16(v);
        hi[i] = h;
        lo[i] = __float2bfloat16(v - __bfloat162float(h));
    }
}
__global__ void split_fx(const float* __restrict__ x,
                         __nv_bfloat16* __restrict__ hi,
                         __nv_bfloat16* __restrict__ lo,
                         const int* __restrict__ flen){
    int i = blockIdx.x*256 + threadIdx.x;
    int t   = (i >> 8) % LSEQ;
    int row = i / (LSEQ*HD);
    if (t >= flen[row]) return;
    float v = x[i];
    __nv_bfloat16 h = __float2bfloat16(v);
    hi[i] = h;
    lo[i] = __float2bfloat16(v - __bfloat162float(h));
}

// =====================================================================
// Big x-GEMM (layer 0), cp.async double-buffered, 2 CTAs/SM.
// grid (8 units, 16 seqgroups, 50 t); early exit when t >= gmax[sg].
// =====================================================================
__global__ __launch_bounds__(256, 2) void hmma_big(
    const __nv_bfloat16* __restrict__ Ah, const __nv_bfloat16* __restrict__ Al,
    const __nv_bfloat16* __restrict__ Bh, const __nv_bfloat16* __restrict__ Bl,
    float* __restrict__ GI)
{
    const int sg = blockIdx.y;
    const int t  = blockIdx.z;
    if (t >= g_gmax[sg]) return;

    extern __shared__ char smraw[];
    __shared__ int perm_s[128];
    const uint32_t sb = smem_u32(smraw);
    const int tid  = threadIdx.x;
    const int lane = tid & 31, warp = tid >> 5;
    const int wm = warp >> 1, wn = warp & 1;
    const int ubu = blockIdx.x * 32;

    if (tid < 128) perm_s[tid] = g_perm[sg*128 + tid];
    __syncthreads();

    const int grp = lane >> 3, rr = lane & 7;
    const int a_m = (grp & 1)*8 + rr, a_k = (grp >> 1)*8;
    const int b_n = (grp >> 1)*8 + rr, b_k = (grp & 1)*8;

    float c[2][6][4];
    #pragma unroll
    for (int mt = 0; mt < 2; ++mt)
        #pragma unroll
        for (int nt = 0; nt < 6; ++nt)
            #pragma unroll
            for (int q = 0; q < 4; ++q) c[mt][nt][q] = 0.f;

    stageA_seq(sb + BIG_ASH, sb + BIG_ASL, Ah, Al, perm_s, t, 0, tid);
    stageB_cp(sb + BIG_BSH, sb + BIG_BSL, Bh, Bl, ubu, 0, tid);
    CP_COMMIT();

    for (int kc = 0; kc < 8; ++kc) {
        const int buf = kc & 1;
        if (kc < 7) {
            const int nb = buf ^ 1;
            stageA_seq(sb + BIG_ASH + nb*10240u, sb + BIG_ASL + nb*10240u,
                       Ah, Al, perm_s, t, (kc+1)*32, tid);
            stageB_cp(sb + BIG_BSH + nb*7680u, sb + BIG_BSL + nb*7680u,
                      Bh, Bl, ubu, (kc+1)*32, tid);
            CP_COMMIT();
            CP_WAIT1();
        } else {
            CP_WAIT0();
        }
        __syncthreads();
        mma_chunk(c, sb + BIG_ASH + buf*10240u, sb + BIG_ASL + buf*10240u,
                     sb + BIG_BSH + buf*7680u,  sb + BIG_BSL + buf*7680u,
                  a_m, a_k, b_n, b_k, wm, wn, 40, 0);
        __syncthreads();
    }

    const size_t colbase = (size_t)blockIdx.x * 96;
    #pragma unroll
    for (int mt = 0; mt < 2; ++mt)
        #pragma unroll
        for (int nt = 0; nt < 6; ++nt) {
            int rl = wm*32 + mt*16 + (lane >> 2);
            int cl = wn*48 + nt*8 + ((lane & 3) << 1);
            size_t r0 = ((size_t)perm_s[rl]*LSEQ + t)*G3;
            size_t r1 = ((size_t)perm_s[rl+8]*LSEQ + t)*G3;
            *(float2*)&GI[r0 + colbase + cl] = make_float2(c[mt][nt][0], c[mt][nt][1]);
            *(float2*)&GI[r1 + colbase + cl] = make_float2(c[mt][nt][2], c[mt][nt][3]);
        }
}

// =====================================================================
// Steal one layer-1 x-GEMM tile inside gru0 (GRU smem layout), gated on
// resident L0 rowgroup counters.
// =====================================================================
__device__ __noinline__ void do_tile(unsigned widx, uint32_t sb, int* perm2_s)
{
    const int tid = threadIdx.x;
    const int lane = tid & 31, warp = tid >> 5;
    const int wm = warp >> 1, wn = warp & 1;
    const int t   = (int)(widx / 128u);
    const int sg  = (int)((widx / 8u) % 16u);
    const int ubx = (int)(widx % 8u);
    if (t >= g_gmax[sg]) return;

    if (tid == 0) {
        const unsigned tgt = 8u*(unsigned)(t+1);
        while (ld_acq(&g_cnt[sg]) < tgt) __nanosleep(64);
    }
    if (tid < 128) perm2_s[tid] = g_perm[sg*128 + tid];
    __syncthreads();

    const int grp = lane >> 3, rr = lane & 7;
    const int a_m = (grp & 1)*8 + rr, a_k = (grp >> 1)*8;
    const int b_n = (grp >> 1)*8 + rr, b_k = (grp & 1)*8;

    float c[2][6][4];
    #pragma unroll
    for (int mt = 0; mt < 2; ++mt)
        #pragma unroll
        for (int nt = 0; nt < 6; ++nt)
            #pragma unroll
            for (int q = 0; q < 4; ++q) c[mt][nt][q] = 0.f;

    stageA_seq(sb + GRU_ASH, sb + GRU_ASL, g_X1h, g_X1l, perm2_s, t, 0, tid);
    stageB_cp(sb + STL_BH, sb + STL_BL, g_Wh[2], g_Wl[2], ubx*32, 0, tid);
    CP_COMMIT();

    for (int kc = 0; kc < 8; ++kc) {
        const int buf = kc & 1;
        if (kc < 7) {
            const int nb = buf ^ 1;
            stageA_seq(sb + GRU_ASH + nb*10240u, sb + GRU_ASL + nb*10240u,
                       g_X1h, g_X1l, perm2_s, t, (kc+1)*32, tid);
            stageB_cp(sb + STL_BH + nb*7680u, sb + STL_BL + nb*7680u,
                      g_Wh[2], g_Wl[2], ubx*32, (kc+1)*32, tid);
            CP_COMMIT();
            CP_WAIT1();
        } else {
            CP_WAIT0();
        }
        __syncthreads();
        mma_chunk(c, sb + GRU_ASH + buf*10240u, sb + GRU_ASL + buf*10240u,
                     sb + STL_BH + buf*7680u,  sb + STL_BL + buf*7680u,
                  a_m, a_k, b_n, b_k, wm, wn, 40, 0);
        __syncthreads();
    }

    const size_t cb = (size_t)ubx * 96;
    #pragma unroll
    for (int mt = 0; mt < 2; ++mt)
        #pragma unroll
        for (int nt = 0; nt < 6; ++nt) {
            int rl = wm*32 + mt*16 + (lane >> 2);
            int cl = wn*48 + nt*8 + ((lane & 3) << 1);
            size_t r0 = ((size_t)perm2_s[rl]*LSEQ + t)*G3;
            size_t r1 = ((size_t)perm2_s[rl+8]*LSEQ + t)*G3;
            *(float2*)&g_GI2[r0 + cb + cl] = make_float2(c[mt][nt][0], c[mt][nt][1]);
            *(float2*)&g_GI2[r1 + cb + cl] = make_float2(c[mt][nt][2], c[mt][nt][3]);
        }
    __syncthreads();
}

// =====================================================================
// Persistent GRU recurrence. Cluster (1,8) = one rowgroup (8 unit-CTAs),
// per-step sync via barrier.cluster. LAYER 0 releases g_cnt (gates the
// stolen L1 tiles) and post-rec drains the L1 tile queue.
// =====================================================================
template<int LAYER>
__global__ void __cluster_dims__(1, 8, 1) __launch_bounds__(256) gru_persist(
    const int* __restrict__ flen,
    const float* __restrict__ bih, const float* __restrict__ bhh)
{
    extern __shared__ char smraw[];
    __shared__ int perm_s[128];
    __shared__ int flen_s[128];
    __shared__ int perm2_s[128];
    __shared__ unsigned act_s;
    const uint32_t sb = smem_u32(smraw);
    unsigned short* Bsh = (unsigned short*)(smraw + GRU_BSH);
    unsigned short* Bsl = (unsigned short*)(smraw + GRU_BSL);
    float* Cs = (float*)(smraw + GRU_CS);
    const uint32_t csb = sb + GRU_CS;

    const int tid  = threadIdx.x;
    const int lane = tid & 31, warp = tid >> 5;
    const int wm = warp >> 1, wn = warp & 1;
    const int rg   = blockIdx.x;
    const int ubu  = blockIdx.y * 32;
    const int tmax = g_gmax[rg];

    if (tid < 128) {
        int p = g_perm[rg*128 + tid];
        perm_s[tid] = p;
        flen_s[tid] = flen[p];
    }

    const __nv_bfloat16* Whh_h = g_Wh[LAYER ? 3 : 1];
    const __nv_bfloat16* Whh_l = g_Wl[LAYER ? 3 : 1];
    const float* GIl = LAYER ? g_GI2 : g_GI;

    // ---- load Whh tile (resident for all steps) ----
    for (int idx = tid; idx < 96*32; idx += 256) {
        int p = idx >> 5, ks = (idx & 31) << 3;
        int w = (p >> 5)*HD + ubu + (p & 31);
        *(uint4*)&Bsh[p*SM_B_STRIDE + ks] = *(const uint4*)&Whh_h[(size_t)w*HD + ks];
        *(uint4*)&Bsl[p*SM_B_STRIDE + ks] = *(const uint4*)&Whh_l[(size_t)w*HD + ks];
    }
    __syncthreads();

    const int grp = lane >> 3, rr = lane & 7;
    const int a_m = (grp & 1)*8 + rr, a_k = (grp >> 1)*8;
    const int b_n = (grp >> 1)*8 + rr, b_k = (grp & 1)*8;

    const int jl = tid & 31;
    const int j  = ubu + jl;
    const float b_r  = bih[j]      + bhh[j];
    const float b_z  = bih[HD+j]   + bhh[HD+j];
    const float bi_n = bih[2*HD+j];
    const float bh_n = bhh[2*HD+j];
    const size_t colbase = (size_t)blockIdx.y * 96;

    for (int t = 0; t < tmax; ++t) {
        const int pa = t & 1, pb = (t+1) & 1;
        const __nv_bfloat16* Ahp = g_Hh[pa];
        const __nv_bfloat16* Alp = g_Hl[pa];
        __nv_bfloat16* Hnh = g_Hh[pb];
        __nv_bfloat16* Hnl = g_Hl[pb];

        float c[2][6][4];
        #pragma unroll
        for (int mt = 0; mt < 2; ++mt)
            #pragma unroll
            for (int nt = 0; nt < 6; ++nt)
                #pragma unroll
                for (int q = 0; q < 4; ++q) c[mt][nt][q] = 0.f;

        if (t > 0) {
            stageA_row(sb + GRU_ASH, sb + GRU_ASL, Ahp, Alp, perm_s, 0, tid);
            stageGI_piece(csb, GIl, perm_s, t, colbase, 0, tid);
            CP_COMMIT();
            for (int kc = 0; kc < 8; ++kc) {
                const int buf = kc & 1;
                if (kc < 7) {
                    const int nb = buf ^ 1;
                    stageA_row(sb + GRU_ASH + nb*10240u, sb + GRU_ASL + nb*10240u,
                               Ahp, Alp, perm_s, (kc+1)*32, tid);
                    stageGI_piece(csb, GIl, perm_s, t, colbase, kc+1, tid);
                    CP_COMMIT();
                    CP_WAIT1();
                } else {
                    CP_WAIT0();
                }
                __syncthreads();
                mma_chunk(c, sb + GRU_ASH + buf*10240u, sb + GRU_ASL + buf*10240u,
                             sb + GRU_BSH, sb + GRU_BSL,
                          a_m, a_k, b_n, b_k, wm, wn, SM_B_STRIDE, kc*32);
                __syncthreads();
            }
        } else {
            #pragma unroll
            for (int pc = 0; pc < 8; ++pc)
                stageGI_piece(csb, GIl, perm_s, t, colbase, pc, tid);
            CP_COMMIT();
            CP_WAIT0();
            __syncthreads();
        }

        // ---- merge fragments: r/z add into Cs, n store to hh_n column ----
        #pragma unroll
        for (int mt = 0; mt < 2; ++mt)
            #pragma unroll
            for (int nt = 0; nt < 6; ++nt) {
                int rl = wm*32 + mt*16 + (lane >> 2);
                int cl = wn*48 + nt*8 + ((lane & 3) << 1);
                const bool is_n = (cl >= 64);
                const int ccl = is_n ? cl + 32 : cl;
                float2* p0 = (float2*)&Cs[rl*128 + ccl];
                float2* p1 = (float2*)&Cs[(rl+8)*128 + ccl];
                if (is_n) {
                    *p0 = make_float2(c[mt][nt][0], c[mt][nt][1]);
                    *p1 = make_float2(c[mt][nt][2], c[mt][nt][3]);
                } else {
                    float2 v0 = *p0, v1 = *p1;
                    *p0 = make_float2(v0.x + c[mt][nt][0], v0.y + c[mt][nt][1]);
                    *p1 = make_float2(v1.x + c[mt][nt][2], v1.y + c[mt][nt][3]);
                }
            }
        __syncthreads();

        // ---- gate epilogue ----
        #pragma unroll
        for (int i = 0; i < 16; ++i) {
            const int rl  = (tid >> 5) + i*8;
            const int row = perm_s[rl];
            const float r = fast_sigmoid(Cs[rl*128 + jl]      + b_r);
            const float z = fast_sigmoid(Cs[rl*128 + 32 + jl] + b_z);
            const float n = fast_tanh(Cs[rl*128 + 64 + jl] + bi_n +
                                      r*(Cs[rl*128 + 96 + jl] + bh_n));
            float hp = 0.f;
            if (t > 0)
                hp = __bfloat162float(Ahp[(size_t)row*HD + j]) +
                     __bfloat162float(Alp[(size_t)row*HD + j]);
            const float h  = (1.f - z)*n + z*hp;
            __nv_bfloat16 hh = __float2bfloat16(h);
            __nv_bfloat16 hl = __float2bfloat16(h - __bfloat162float(hh));
            Hnh[(size_t)row*HD + j] = hh;
            Hnl[(size_t)row*HD + j] = hl;
            if (LAYER == 0) {
                if (t < flen_s[rl]) {            // dead X1 slots stay zero
                    size_t xi = ((size_t)row*LSEQ + t)*HD + j;
                    g_X1h[xi] = hh; g_X1l[xi] = hl;
                }
            } else {
                if (t == flen_s[rl] - 1) g_FL[(size_t)row*HD + j] = h;
            }
        }

        // ---- step barrier: release for stealers (L0), cluster-sync ----
        __threadfence();
        __syncthreads();
        if (LAYER == 0 && tid == 0) red_release(&g_cnt[rg]);
        if (t + 1 < tmax) {
            CLUSTER_ARRIVE();
            CLUSTER_WAIT();
        }
    }

    // ---- LAYER 0: post-recurrence drain of layer-1 GEMM tiles ----
    if (LAYER == 0) {
        for (;;) {
            __syncthreads();
            if (tid == 0) {
                unsigned w = atomicAdd(&g_q1, 1u);
                act_s = (w < (unsigned)NT_Q) ? (w + 2u) : 1u;
            }
            __syncthreads();
            const unsigned a = act_s;
            if (a == 1u) break;
            do_tile(a - 2u, sb, perm2_s);
        }
    }
}

// ---------------- fp32 tail GEMM (small) ----------------
template<int TRANSW>
__global__ __launch_bounds__(256) void sgemm_tn(
    const float* __restrict__ A, const float* __restrict__ W, float* __restrict__ C,
    int M, int N, int K)
{
    __shared__ float As[32][68];
    __shared__ float Bs[32][68];
    const int tid = threadIdx.x;
    const int tx = tid & 15, ty = tid >> 4;
    const int mb = blockIdx.x * 64, nb = blockIdx.y * 64;

    float2 acc[4][2];
    #pragma unroll
    for (int i = 0; i < 4; ++i) { acc[i][0] = make_float2(0.f,0.f); acc[i][1] = make_float2(0.f,0.f); }

    for (int kc = 0; kc < K; kc += 32) {
        #pragma unroll
        for (int q = 0; q < 2; ++q) {
            int idx = q*256 + tid;
            int row = idx >> 3;
            int k4  = (idx & 7) << 2;
            const float4 v = *reinterpret_cast<const float4*>(&A[(size_t)(mb+row)*K + kc + k4]);
            As[k4+0][row] = v.x; As[k4+1][row] = v.y; As[k4+2][row] = v.z; As[k4+3][row] = v.w;
        }
        if (!TRANSW) {
            #pragma unroll
            for (int q = 0; q < 2; ++q) {
                int idx = q*256 + tid;
                int n  = idx >> 3;
                int k4 = (idx & 7) << 2;
                const float4 v = *reinterpret_cast<const float4*>(&W[(size_t)(nb+n)*K + kc + k4]);
                Bs[k4+0][n] = v.x; Bs[k4+1][n] = v.y; Bs[k4+2][n] = v.z; Bs[k4+3][n] = v.w;
            }
        } else {
            #pragma unroll
            for (int q = 0; q < 2; ++q) {
                int idx = q*256 + tid;
                int k  = idx >> 4;
                int n4 = (idx & 15) << 2;
                const float4 v = *reinterpret_cast<const float4*>(&W[(size_t)(kc+k)*N + nb + n4]);
                *reinterpret_cast<float4*>(&Bs[k][n4]) = v;
            }
        }
        __syncthreads();
        #pragma unroll
        for (int k = 0; k < 32; ++k) {
            const float4 a4 = *reinterpret_cast<const float4*>(&As[k][ty<<2]);
            const float4 b4 = *reinterpret_cast<const float4*>(&Bs[k][tx<<2]);
            const float2 b0 = make_float2(b4.x, b4.y);
            const float2 b1 = make_float2(b4.z, b4.w);
            float av[4] = {a4.x, a4.y, a4.z, a4.w};
            #pragma unroll
            for (int i = 0; i < 4; ++i) {
                float2 aa = make_float2(av[i], av[i]);
                acc[i][0] = ffma2(aa, b0, acc[i][0]);
                acc[i][1] = ffma2(aa, b1, acc[i][1]);
            }
        }
        __syncthreads();
    }
    #pragma unroll
    for (int i = 0; i < 4; ++i) {
        const int row = mb + (ty<<2) + i;
        float4 o;
        o.x = acc[i][0].x; o.y = acc[i][0].y; o.z = acc[i][1].x; o.w = acc[i][1].y;
        *reinterpret_cast<float4*>(&C[(size_t)row*N + nb + (tx<<2)]) = o;
    }
}

__global__ void build_cat(const float* __restrict__ self_x,
                          const float* __restrict__ FL,
                          float* __restrict__ CAT){
    const int m = blockIdx.x, tid = threadIdx.x;
    CAT[(size_t)m*2*HD + tid]      = self_x[(size_t)(m>>5)*HD + tid];
    CAT[(size_t)m*2*HD + HD + tid] = FL[(size_t)m*HD + tid];
}

__global__ __launch_bounds__(256) void tf_kernel(
    const float* __restrict__ common_x, const float* __restrict__ common_time,
    const float* __restrict__ V, const int* __restrict__ clen, float* __restrict__ TF)
{
    const int m = blockIdx.x;
    __shared__ float vs[HD];
    __shared__ float wsum[8];
    const int tid = threadIdx.x;
    vs[tid] = V[(size_t)m*HD + tid];
    __syncthreads();
    const int warp = tid >> 5, lane = tid & 31;
    const int cl = clen[m];
    float acc = 0.f;
    for (int s = warp; s < cl; s += 8) {
        const float* cx = common_x + ((size_t)m*SSEQ + s)*HD;
        float p = 0.f;
        #pragma unroll
        for (int q = 0; q < 8; ++q) p += cx[lane + 32*q] * vs[lane + 32*q];
        #pragma unroll
        for (int off = 16; off; off >>= 1) p += __shfl_xor_sync(0xffffffffu, p, off);
        if (lane == 0)
            acc += softplus_f(p) * expf(-common_time[(size_t)m*SSEQ + s]);
    }
    if (lane == 0) wsum[warp] = acc;
    __syncthreads();
    if (tid == 0) {
        float s = 0.f;
        for (int w = 0; w < 8; ++w) s += wsum[w];
        TF[m] = s;
    }
}

__global__ __launch_bounds__(256) void out_kernel(
    const float* __restrict__ TF, const float* __restrict__ FL,
    const int* __restrict__ fnum, float* __restrict__ out)
{
    const int b = blockIdx.x;
    __shared__ float w[MAXF];
    const int tid = threadIdx.x;
    const int fn = fnum[b];
    if (tid < MAXF) w[tid] = (tid < fn) ? TF[b*MAXF + tid] : 0.f;
    __syncthreads();
    if (tid == 0) {
        float mx = w[0];
        for (int f = 1; f < MAXF; ++f) mx = fmaxf(mx, w[f]);
        float s = 0.f;
        for (int f = 0; f < MAXF; ++f) { float e = expf(w[f] - mx); w[f] = e; s += e; }
        float inv = 1.f / s;
        for (int f = 0; f < MAXF; ++f) w[f] *= inv;
    }
    __syncthreads();
    float acc = 0.f;
    for (int f = 0; f < fn; ++f)
        acc += w[f] * FL[(size_t)(b*MAXF + f)*HD + tid];
    out[(size_t)b*HD + tid] = acc;
}

// ---------------- host launcher ----------------
extern "C" void kernel_launch(void* const* d_in, const int* in_sizes, int n_in,
                              void* d_out, int out_size)
{
    const float* self_x      = (const float*)d_in[0];
    const float* common_x    = (const float*)d_in[1];
    const float* common_time = (const float*)d_in[2];
    const float* friend_x    = (const float*)d_in[3];
    const float* Wih0 = (const float*)d_in[4];
    const float* Whh0 = (const float*)d_in[5];
    const float* bih0 = (const float*)d_in[6];
    const float* bhh0 = (const float*)d_in[7];
    const float* Wih1 = (const float*)d_in[8];
    const float* Whh1 = (const float*)d_in[9];
    const float* bih1 = (const float*)d_in[10];
    const float* bhh1 = (const float*)d_in[11];
    const float* Wf   = (const float*)d_in[12];
    const float* Wb   = (const float*)d_in[13];
    const int*   flen = (const int*)d_in[14];
    const int*   fnum = (const int*)d_in[15];
    const int*   clen = (const int*)d_in[16];
    float* out = (float*)d_out;

    float *GI, *FL, *CAT, *SF, *V, *TF;
    __nv_bfloat16 *FXh, *FXl, *Wh, *Wl;
    cudaGetSymbolAddress((void**)&GI,  g_GI);
    cudaGetSymbolAddress((void**)&FXh, g_FXh);
    cudaGetSymbolAddress((void**)&FXl, g_FXl);
    cudaGetSymbolAddress((void**)&Wh,  g_Wh);
    cudaGetSymbolAddress((void**)&Wl,  g_Wl);
    cudaGetSymbolAddress((void**)&FL,  g_FL);
    cudaGetSymbolAddress((void**)&CAT, g_CAT);
    cudaGetSymbolAddress((void**)&SF,  g_SF);
    cudaGetSymbolAddress((void**)&V,   g_V);
    cudaGetSymbolAddress((void**)&TF,  g_TF);

    const float* Wsrc[4] = {Wih0, Whh0, Wih1, Whh1};

    static bool init_done = false;
    if (!init_done) {
        cudaFuncSetAttribute(hmma_big,       cudaFuncAttributeMaxDynamicSharedMemorySize, BIG_DYN);
        cudaFuncSetAttribute(gru_persist<0>, cudaFuncAttributeMaxDynamicSharedMemorySize, GRU_DYN);
        cudaFuncSetAttribute(gru_persist<1>, cudaFuncAttributeMaxDynamicSharedMemorySize, GRU_DYN);
        init_done = true;
    }

    // --- sort rows by flen + reset counters/queue ---
    rank_kernel<<<NSEQ/256, 256>>>(flen);

    // --- conversions ---
    split_fx<<<((size_t)MTOT*HD + 255)/256, 256>>>(friend_x, FXh, FXl, flen);
    for (int w = 0; w < 4; ++w)
        split_kernel<<<(G3*HD + 255)/256, 256>>>(Wsrc[w], Wh + (size_t)w*G3*HD,
                                                 Wl + (size_t)w*G3*HD, G3*HD);

    // ---- layer 0 big GEMM ----
    hmma_big<<<dim3(8, 16, LSEQ), 256, BIG_DYN>>>(FXh, FXl,
        Wh + 0*(size_t)G3*HD, Wl + 0*(size_t)G3*HD, GI);

    // ---- layer 0 recurrence + post-rec steal of layer-1 x-GEMM tiles ----
    gru_persist<0><<<dim3(16, 8), 256, GRU_DYN>>>(flen, bih0, bhh0);

    // ---- layer 1 recurrence (GI2 fully materialized by gru0) ----
    gru_persist<1><<<dim3(16, 8), 256, GRU_DYN>>>(flen, bih1, bhh1);

    // ---- tail ----
    build_cat<<<NSEQ, 256>>>(self_x, FL, CAT);
    sgemm_tn<0><<<dim3(NSEQ/64, HD/64), 256>>>(CAT, Wf, SF, NSEQ, HD, 2*HD);
    sgemm_tn<1><<<dim3(NSEQ/64, HD/64), 256>>>(SF,  Wb, V,  NSEQ, HD, HD);
    tf_kernel<<<NSEQ, 256>>>(common_x, common_time, V, clen, TF);
    out_kernel<<<NBATCH, 256>>>(TF, FL, fnum, out);
}

// round 15
// speedup vs baseline: 1.1181x; 1.0926x over previous
#include <cuda_runtime.h>
#include <cuda_bf16.h>
#include <cstdint>
#include <math.h>

#define HD    256
#define LSEQ  50
#define SSEQ  50
#define NBATCH 64
#define MAXF  32
#define NSEQ  (NBATCH*MAXF)            // 2048
#define MTOT  (NSEQ*LSEQ)              // 102400
#define G3    (3*HD)                   // 768
#define NTILES (16*LSEQ*8)             // L1 GEMM tile space

// ---------------- device scratch ----------------
__device__ __nv_bfloat16  g_Hh[2][NSEQ*HD];
__device__ __nv_bfloat16  g_Hl[2][NSEQ*HD];
__device__ float          g_GI[(size_t)MTOT*G3];    // layer-0 pre-activations
__device__ float          g_GI2[(size_t)MTOT*G3];   // layer-1 pre-activations
__device__ __nv_bfloat16  g_FXh[(size_t)MTOT*HD];
__device__ __nv_bfloat16  g_FXl[(size_t)MTOT*HD];
__device__ __nv_bfloat16  g_X1h[(size_t)MTOT*HD];
__device__ __nv_bfloat16  g_X1l[(size_t)MTOT*HD];
__device__ __nv_bfloat16  g_Wh[4][G3*HD];
__device__ __nv_bfloat16  g_Wl[4][G3*HD];
__device__ float g_FL[NSEQ*HD];
__device__ float g_SF[NSEQ*HD];
__device__ float g_V[NSEQ*HD];
__device__ float g_TF[NSEQ];
__device__ unsigned g_cnt[32];            // rowgroup step counters (16 per layer)
__device__ unsigned g_work;               // L1 GEMM tile queue head
__device__ int g_perm[NSEQ];
__device__ int g_gmax[16];

// ---------------- helpers ----------------
__device__ __forceinline__ float fast_sigmoid(float x){
    return __fdividef(1.f, 1.f + __expf(-x));
}
__device__ __forceinline__ float fast_tanh(float x){
    return 1.f - __fdividef(2.f, __expf(2.f*x) + 1.f);
}
__device__ __forceinline__ float softplus_f(float x){
    return (x > 20.f) ? x : log1pf(expf(x));
}
__device__ __forceinline__ float2 ffma2(float2 a, float2 b, float2 c){
    unsigned long long ua = reinterpret_cast<unsigned long long&>(a);
    unsigned long long ub = reinterpret_cast<unsigned long long&>(b);
    unsigned long long uc = reinterpret_cast<unsigned long long&>(c);
    unsigned long long ud;
    asm("fma.rn.f32x2 %0, %1, %2, %3;" : "=l"(ud) : "l"(ua), "l"(ub), "l"(uc));
    return reinterpret_cast<float2&>(ud);
}
__device__ __forceinline__ uint32_t smem_u32(const void* p){
    return (uint32_t)__cvta_generic_to_shared(p);
}
__device__ __forceinline__ void ldsm_x4(unsigned* r, uint32_t addr){
    asm volatile("ldmatrix.sync.aligned.m8n8.x4.shared.b16 {%0,%1,%2,%3}, [%4];\n"
        : "=r"(r[0]), "=r"(r[1]), "=r"(r[2]), "=r"(r[3]) : "r"(addr));
}
__device__ __forceinline__ void mma16816(float* c, const unsigned* a, const unsigned* b){
    asm volatile("mma.sync.aligned.m16n8k16.row.col.f32.bf16.bf16.f32 "
        "{%0,%1,%2,%3}, {%4,%5,%6,%7}, {%8,%9}, {%0,%1,%2,%3};\n"
        : "+f"(c[0]), "+f"(c[1]), "+f"(c[2]), "+f"(c[3])
        : "r"(a[0]), "r"(a[1]), "r"(a[2]), "r"(a[3]), "r"(b[0]), "r"(b[1]));
}
__device__ __forceinline__ unsigned ld_acq(const unsigned* p){
    unsigned v;
    asm volatile("ld.acquire.gpu.u32 %0, [%1];" : "=r"(v) : "l"(p) : "memory");
    return v;
}
__device__ __forceinline__ void red_release(unsigned* p){
    asm volatile("red.release.gpu.global.add.u32 [%0], %1;" :: "l"(p), "r"(1u) : "memory");
}
__device__ __forceinline__ void cp16(uint32_t dst, const void* src){
    asm volatile("cp.async.cg.shared.global [%0], [%1], 16;" :: "r"(dst), "l"(src) : "memory");
}
#define CP_COMMIT() asm volatile("cp.async.commit_group;" ::: "memory")
#define CP_WAIT1()  asm volatile("cp.async.wait_group 1;" ::: "memory")
#define CP_WAIT0()  asm volatile("cp.async.wait_group 0;" ::: "memory")

// ---------------- sort rows by flen (descending, deterministic) ----------------
__global__ void rank_kernel(const int* __restrict__ flen){
    __shared__ int fl_s[NSEQ];
    for (int i = threadIdx.x; i < NSEQ; i += 256) fl_s[i] = flen[i];
    __syncthreads();
    const int i = blockIdx.x*256 + threadIdx.x;
    const int f = fl_s[i];
    int r = 0;
    for (int jj = 0; jj < NSEQ; ++jj) {
        int fj = fl_s[jj];
        r += (fj > f) || (fj == f && jj < i);
    }
    g_perm[r] = i;
    if ((r & 127) == 0) g_gmax[r >> 7] = f;
    if (blockIdx.x == 0 && threadIdx.x < 32) g_cnt[threadIdx.x] = 0u;
    if (blockIdx.x == 0 && threadIdx.x == 0) g_work = 0u;
}

// ---------------- staging (cp.async) ----------------
__device__ __forceinline__ void stageA_seq(uint32_t sA_h, uint32_t sA_l,
        const __nv_bfloat16* __restrict__ Ah, const __nv_bfloat16* __restrict__ Al,
        const int* __restrict__ perm_s, int t, int kk, int tid){
    #pragma unroll
    for (int q = 0; q < 2; ++q) {
        int idx = q*256 + tid;
        int r = idx >> 2, ks = (idx & 3) << 3;
        size_t s = ((size_t)perm_s[r]*LSEQ + t)*HD + kk + ks;
        uint32_t d = (uint32_t)(r*40 + ks)*2u;
        cp16(sA_h + d, Ah + s);
        cp16(sA_l + d, Al + s);
    }
}
__device__ __forceinline__ void stageA_row(uint32_t sA_h, uint32_t sA_l,
        const __nv_bfloat16* __restrict__ Ah, const __nv_bfloat16* __restrict__ Al,
        const int* __restrict__ perm_s, int kk, int tid){
    #pragma unroll
    for (int q = 0; q < 2; ++q) {
        int idx = q*256 + tid;
        int r = idx >> 2, ks = (idx & 3) << 3;
        size_t s = (size_t)perm_s[r]*HD + kk + ks;
        uint32_t d = (uint32_t)(r*40 + ks)*2u;
        cp16(sA_h + d, Ah + s);
        cp16(sA_l + d, Al + s);
    }
}
__device__ __forceinline__ void stageB_cp(uint32_t sB_h, uint32_t sB_l,
        const __nv_bfloat16* __restrict__ Bh, const __nv_bfloat16* __restrict__ Bl,
        int ubu, int kk, int tid){
    #pragma unroll
    for (int q = 0; q < 2; ++q) {
        int idx = q*256 + tid;
        if (idx < 384) {
            int p = idx >> 2, ks = (idx & 3) << 3;
            int w = (p >> 5)*HD + ubu + (p & 31);
            size_t s = (size_t)w*HD + kk + ks;
            uint32_t d = (uint32_t)(p*40 + ks)*2u;
            cp16(sB_h + d, Bh + s);
            cp16(sB_l + d, Bl + s);
        }
    }
}
__device__ __forceinline__ void stageGI_piece(uint32_t cs, const float* __restrict__ GI,
        const int* __restrict__ perm_s, int t, size_t colbase, int piece, int tid){
    #pragma unroll
    for (int q = 0; q < 2; ++q) {
        int i = q*256 + tid;
        if (i < 384) {
            int i2 = piece*384 + i;
            int rl = i2 / 24, c16 = i2 % 24;
            const float* src = GI + ((size_t)perm_s[rl]*LSEQ + t)*G3 + colbase + c16*4;
            cp16(cs + (uint32_t)(rl*128 + c16*4)*4u, src);
        }
    }
}

// ---------------- MMA on one staged 32-k chunk (3-term hi/lo) ----------------
__device__ __forceinline__ void mma_chunk(
    float (&c)[2][6][4],
    uint32_t aAsh, uint32_t aAsl, uint32_t aBsh, uint32_t aBsl,
    int a_m, int a_k, int b_n, int b_k, int wm, int wn, int bstride, int bkoff)
{
    #pragma unroll
    for (int kt = 0; kt < 2; ++kt) {
        unsigned ah[2][4], al[2][4], bh[3][4], bl[3][4];
        #pragma unroll
        for (int mt = 0; mt < 2; ++mt) {
            uint32_t off = 2u*((wm*32 + mt*16 + a_m)*40 + kt*16 + a_k);
            ldsm_x4(ah[mt], aAsh + off);
            ldsm_x4(al[mt], aAsl + off);
        }
        #pragma unroll
        for (int np = 0; np < 3; ++np) {
            uint32_t off = 2u*((wn*48 + np*16 + b_n)*bstride + bkoff + kt*16 + b_k);
            ldsm_x4(bh[np], aBsh + off);
            ldsm_x4(bl[np], aBsl + off);
        }
        #pragma unroll
        for (int mt = 0; mt < 2; ++mt)
            #pragma unroll
            for (int nt = 0; nt < 6; ++nt) {
                const unsigned* B1 = &bh[nt>>1][(nt&1)*2];
                const unsigned* B2 = &bl[nt>>1][(nt&1)*2];
                mma16816(c[mt][nt], ah[mt], B1);
                mma16816(c[mt][nt], al[mt], B1);
                mma16816(c[mt][nt], ah[mt], B2);
            }
    }
}

// ---------------- hi/lo split conversions ----------------
__global__ void split_kernel(const float* __restrict__ x,
                             __nv_bfloat16* __restrict__ hi,
                             __nv_bfloat16* __restrict__ lo, int n){
    int i = blockIdx.x*256 + threadIdx.x;
    if (i < n){
        float v = x[i];
        __nv_bfloat16 h = __float2bfloat16(v);
        hi[i] = h;
        lo[i] = __float2bfloat16(v - __bfloat162float(h));
    }
}
__global__ void split_fx(const float* __restrict__ x,
                         __nv_bfloat16* __restrict__ hi,
                         __nv_bfloat16* __restrict__ lo,
                         const int* __restrict__ flen){
    int i = blockIdx.x*256 + threadIdx.x;
    int t   = (i >> 8) % LSEQ;
    int row = i / (LSEQ*HD);
    if (t >= flen[row]) return;
    float v = x[i];
    __nv_bfloat16 h = __float2bfloat16(v);
    hi[i] = h;
    lo[i] = __float2bfloat16(v - __bfloat162float(h));
}

// =====================================================================
// Big x-GEMM (layer 0), cp.async double-buffered, 2 CTAs/SM.
// grid (8 units, 16 seqgroups, 50 t); early exit when t >= gmax[sg].
// =====================================================================
#define BIG_ASH 0u
#define BIG_ASL 20480u
#define BIG_BSH 40960u
#define BIG_BSL 56320u
#define BIG_DYN 71680u

__global__ __launch_bounds__(256, 2) void hmma_big(
    const __nv_bfloat16* __restrict__ Ah, const __nv_bfloat16* __restrict__ Al,
    const __nv_bfloat16* __restrict__ Bh, const __nv_bfloat16* __restrict__ Bl,
    float* __restrict__ GI)
{
    const int sg = blockIdx.y;
    const int t  = blockIdx.z;
    if (t >= g_gmax[sg]) return;

    extern __shared__ char smraw[];
    __shared__ int perm_s[128];
    const uint32_t sb = smem_u32(smraw);
    const int tid  = threadIdx.x;
    const int lane = tid & 31, warp = tid >> 5;
    const int wm = warp >> 1, wn = warp & 1;
    const int ubu = blockIdx.x * 32;

    if (tid < 128) perm_s[tid] = g_perm[sg*128 + tid];
    __syncthreads();

    const int grp = lane >> 3, rr = lane & 7;
    const int a_m = (grp & 1)*8 + rr, a_k = (grp >> 1)*8;
    const int b_n = (grp >> 1)*8 + rr, b_k = (grp & 1)*8;

    float c[2][6][4];
    #pragma unroll
    for (int mt = 0; mt < 2; ++mt)
        #pragma unroll
        for (int nt = 0; nt < 6; ++nt)
            #pragma unroll
            for (int q = 0; q < 4; ++q) c[mt][nt][q] = 0.f;

    stageA_seq(sb + BIG_ASH, sb + BIG_ASL, Ah, Al, perm_s, t, 0, tid);
    stageB_cp(sb + BIG_BSH, sb + BIG_BSL, Bh, Bl, ubu, 0, tid);
    CP_COMMIT();

    for (int kc = 0; kc < 8; ++kc) {
        const int buf = kc & 1;
        if (kc < 7) {
            const int nb = buf ^ 1;
            stageA_seq(sb + BIG_ASH + nb*10240u, sb + BIG_ASL + nb*10240u,
                       Ah, Al, perm_s, t, (kc+1)*32, tid);
            stageB_cp(sb + BIG_BSH + nb*7680u, sb + BIG_BSL + nb*7680u,
                      Bh, Bl, ubu, (kc+1)*32, tid);
            CP_COMMIT();
            CP_WAIT1();
        } else {
            CP_WAIT0();
        }
        __syncthreads();
        mma_chunk(c, sb + BIG_ASH + buf*10240u, sb + BIG_ASL + buf*10240u,
                     sb + BIG_BSH + buf*7680u,  sb + BIG_BSL + buf*7680u,
                  a_m, a_k, b_n, b_k, wm, wn, 40, 0);
        __syncthreads();
    }

    const size_t colbase = (size_t)blockIdx.x * 96;
    #pragma unroll
    for (int mt = 0; mt < 2; ++mt)
        #pragma unroll
        for (int nt = 0; nt < 6; ++nt) {
            int rl = wm*32 + mt*16 + (lane >> 2);
            int cl = wn*48 + nt*8 + ((lane & 3) << 1);
            size_t r0 = ((size_t)perm_s[rl]*LSEQ + t)*G3;
            size_t r1 = ((size_t)perm_s[rl+8]*LSEQ + t)*G3;
            *(float2*)&GI[r0 + colbase + cl] = make_float2(c[mt][nt][0], c[mt][nt][1]);
            *(float2*)&GI[r1 + colbase + cl] = make_float2(c[mt][nt][2], c[mt][nt][3]);
        }
}

// =====================================================================
// Persistent GRU recurrence (per-rowgroup step bound gmax[rg]).
// LAYER 0: after the recurrence, CTAs steal layer-1 x-GEMM tiles from a
// global queue, gated on the resident rowgroup counters.
// =====================================================================
#define GRU_BSH 0u
#define GRU_BSL 50688u
#define GRU_ASH 101376u
#define GRU_ASL 121856u
#define GRU_CS  142336u
#define GRU_DYN 207872u
#define SM_B_STRIDE 264
#define STL_BH  GRU_CS
#define STL_BL  (GRU_CS + 15360u)

template<int LAYER>
__global__ __launch_bounds__(256) void gru_persist(
    const __nv_bfloat16* __restrict__ Whh_h, const __nv_bfloat16* __restrict__ Whh_l,
    const float* __restrict__ GI,
    __nv_bfloat16* __restrict__ Hhb, __nv_bfloat16* __restrict__ Hlb,
    __nv_bfloat16* __restrict__ X1h, __nv_bfloat16* __restrict__ X1l,
    float* __restrict__ FL, const int* __restrict__ flen,
    const float* __restrict__ bih, const float* __restrict__ bhh,
    const __nv_bfloat16* __restrict__ sBh, const __nv_bfloat16* __restrict__ sBl,
    float* __restrict__ GI2)
{
    extern __shared__ char smraw[];
    __shared__ int perm_s[128];
    __shared__ int flen_s[128];
    __shared__ unsigned widx_s;
    const uint32_t sb = smem_u32(smraw);
    float* Cs = (float*)(smraw + GRU_CS);
    const uint32_t csb = sb + GRU_CS;
    unsigned short* Bsh = (unsigned short*)(smraw + GRU_BSH);
    unsigned short* Bsl = (unsigned short*)(smraw + GRU_BSL);

    const int tid  = threadIdx.x;
    const int lane = tid & 31, warp = tid >> 5;
    const int wm = warp >> 1, wn = warp & 1;
    const int rg   = blockIdx.x;
    const int ubu  = blockIdx.y * 32;
    const int tmax = g_gmax[rg];

    if (tid < 128) {
        int p = g_perm[rg*128 + tid];
        perm_s[tid] = p;
        flen_s[tid] = flen[p];
    }

    const int grp = lane >> 3, rr = lane & 7;
    const int a_m = (grp & 1)*8 + rr, a_k = (grp >> 1)*8;
    const int b_n = (grp >> 1)*8 + rr, b_k = (grp & 1)*8;

    // ---- load Whh tile once ----
    for (int idx = tid; idx < 96*32; idx += 256) {
        int p = idx >> 5, ks = (idx & 31) << 3;
        int w = (p >> 5)*HD + ubu + (p & 31);
        *(uint4*)&Bsh[p*SM_B_STRIDE + ks] = *(const uint4*)&Whh_h[(size_t)w*HD + ks];
        *(uint4*)&Bsl[p*SM_B_STRIDE + ks] = *(const uint4*)&Whh_l[(size_t)w*HD + ks];
    }
    __syncthreads();

    const int jl = tid & 31;
    const int j  = ubu + jl;
    const float b_r  = bih[j]      + bhh[j];
    const float b_z  = bih[HD+j]   + bhh[HD+j];
    const float bi_n = bih[2*HD+j];
    const float bh_n = bhh[2*HD+j];
    const size_t colbase = (size_t)blockIdx.y * 96;
    unsigned* cnt = &g_cnt[rg + (LAYER ? 16 : 0)];

    for (int t = 0; t < tmax; ++t) {
        const int pa = t & 1, pb = (t+1) & 1;
        const __nv_bfloat16* Ahp = Hhb + (size_t)pa*NSEQ*HD;
        const __nv_bfloat16* Alp = Hlb + (size_t)pa*NSEQ*HD;
        __nv_bfloat16* Hnh = Hhb + (size_t)pb*NSEQ*HD;
        __nv_bfloat16* Hnl = Hlb + (size_t)pb*NSEQ*HD;

        float c[2][6][4];
        #pragma unroll
        for (int mt = 0; mt < 2; ++mt)
            #pragma unroll
            for (int nt = 0; nt < 6; ++nt)
                #pragma unroll
                for (int q = 0; q < 4; ++q) c[mt][nt][q] = 0.f;

        if (t > 0) {
            stageA_row(sb + GRU_ASH, sb + GRU_ASL, Ahp, Alp, perm_s, 0, tid);
            stageGI_piece(csb, GI, perm_s, t, colbase, 0, tid);
            CP_COMMIT();
            for (int kc = 0; kc < 8; ++kc) {
                const int buf = kc & 1;
                if (kc < 7) {
                    const int nb = buf ^ 1;
                    stageA_row(sb + GRU_ASH + nb*10240u, sb + GRU_ASL + nb*10240u,
                               Ahp, Alp, perm_s, (kc+1)*32, tid);
                    stageGI_piece(csb, GI, perm_s, t, colbase, kc+1, tid);
                    CP_COMMIT();
                    CP_WAIT1();
                } else {
                    CP_WAIT0();
                }
                __syncthreads();
                mma_chunk(c, sb + GRU_ASH + buf*10240u, sb + GRU_ASL + buf*10240u,
                             sb + GRU_BSH, sb + GRU_BSL,
                          a_m, a_k, b_n, b_k, wm, wn, SM_B_STRIDE, kc*32);
                __syncthreads();
            }
        } else {
            #pragma unroll
            for (int pc = 0; pc < 8; ++pc)
                stageGI_piece(csb, GI, perm_s, t, colbase, pc, tid);
            CP_COMMIT();
            CP_WAIT0();
            __syncthreads();
        }

        // ---- merge fragments: r/z add into Cs, n store to hh_n column ----
        #pragma unroll
        for (int mt = 0; mt < 2; ++mt)
            #pragma unroll
            for (int nt = 0; nt < 6; ++nt) {
                int rl = wm*32 + mt*16 + (lane >> 2);
                int cl = wn*48 + nt*8 + ((lane & 3) << 1);
                const bool is_n = (cl >= 64);
                const int ccl = is_n ? cl + 32 : cl;
                float2* p0 = (float2*)&Cs[rl*128 + ccl];
                float2* p1 = (float2*)&Cs[(rl+8)*128 + ccl];
                if (is_n) {
                    *p0 = make_float2(c[mt][nt][0], c[mt][nt][1]);
                    *p1 = make_float2(c[mt][nt][2], c[mt][nt][3]);
                } else {
                    float2 v0 = *p0, v1 = *p1;
                    *p0 = make_float2(v0.x + c[mt][nt][0], v0.y + c[mt][nt][1]);
                    *p1 = make_float2(v1.x + c[mt][nt][2], v1.y + c[mt][nt][3]);
                }
            }
        __syncthreads();

        // ---- gate epilogue ----
        #pragma unroll
        for (int i = 0; i < 16; ++i) {
            const int rl  = (tid >> 5) + i*8;
            const int row = perm_s[rl];
            const float r = fast_sigmoid(Cs[rl*128 + jl]      + b_r);
            const float z = fast_sigmoid(Cs[rl*128 + 32 + jl] + b_z);
            const float n = fast_tanh(Cs[rl*128 + 64 + jl] + bi_n +
                                      r*(Cs[rl*128 + 96 + jl] + bh_n));
            float hp = 0.f;
            if (t > 0)
                hp = __bfloat162float(Ahp[(size_t)row*HD + j]) +
                     __bfloat162float(Alp[(size_t)row*HD + j]);
            const float h  = (1.f - z)*n + z*hp;
            __nv_bfloat16 hh = __float2bfloat16(h);
            __nv_bfloat16 hl = __float2bfloat16(h - __bfloat162float(hh));
            Hnh[(size_t)row*HD + j] = hh;
            Hnl[(size_t)row*HD + j] = hl;
            if (LAYER == 0) {
                if (t < flen_s[rl]) {            // dead X1 slots stay zero
                    size_t xi = ((size_t)row*LSEQ + t)*HD + j;
                    X1h[xi] = hh; X1l[xi] = hl;
                }
            } else {
                if (t == flen_s[rl] - 1) FL[(size_t)row*HD + j] = h;
            }
        }

        // ---- rowgroup barrier: always release (consumed by stealers), wait unless last ----
        __threadfence();
        __syncthreads();
        if (tid == 0) {
            red_release(cnt);
            if (t + 1 < tmax) {
                const unsigned target = 8u*(unsigned)(t+1);
                while (ld_acq(cnt) < target) __nanosleep(32);
            }
        }
        __syncthreads();
    }

    // =============== LAYER 0: steal layer-1 x-GEMM tiles ===============
    if (LAYER == 0) {
        for (;;) {
            __syncthreads();
            if (tid == 0) widx_s = atomicAdd(&g_work, 1u);
            __syncthreads();
            const unsigned widx = widx_s;
            if (widx >= (unsigned)NTILES) break;
            const int t   = (int)(widx / 128u);      // t ascending: matches availability
            const int sg  = (int)((widx / 8u) % 16u);
            const int ubx = (int)(widx % 8u);
            if (t >= g_gmax[sg]) continue;

            if (tid == 0) {
                const unsigned target = 8u*(unsigned)(t+1);
                while (ld_acq(&g_cnt[sg]) < target) __nanosleep(64);
            }
            if (tid < 128) perm_s[tid] = g_perm[sg*128 + tid];
            __syncthreads();

            float c[2][6][4];
            #pragma unroll
            for (int mt = 0; mt < 2; ++mt)
                #pragma unroll
                for (int nt = 0; nt < 6; ++nt)
                    #pragma unroll
                    for (int q = 0; q < 4; ++q) c[mt][nt][q] = 0.f;

            stageA_seq(sb + GRU_ASH, sb + GRU_ASL, X1h, X1l, perm_s, t, 0, tid);
            stageB_cp(sb + STL_BH, sb + STL_BL, sBh, sBl, ubx*32, 0, tid);
            CP_COMMIT();
            for (int kc = 0; kc < 8; ++kc) {
                const int buf = kc & 1;
                if (kc < 7) {
                    const int nb = buf ^ 1;
                    stageA_seq(sb + GRU_ASH + nb*10240u, sb + GRU_ASL + nb*10240u,
                               X1h, X1l, perm_s, t, (kc+1)*32, tid);
                    stageB_cp(sb + STL_BH + nb*7680u, sb + STL_BL + nb*7680u,
                              sBh, sBl, ubx*32, (kc+1)*32, tid);
                    CP_COMMIT();
                    CP_WAIT1();
                } else {
                    CP_WAIT0();
                }
                __syncthreads();
                mma_chunk(c, sb + GRU_ASH + buf*10240u, sb + GRU_ASL + buf*10240u,
                             sb + STL_BH + buf*7680u,  sb + STL_BL + buf*7680u,
                          a_m, a_k, b_n, b_k, wm, wn, 40, 0);
                __syncthreads();
            }

            const size_t cb2 = (size_t)ubx * 96;
            #pragma unroll
            for (int mt = 0; mt < 2; ++mt)
                #pragma unroll
                for (int nt = 0; nt < 6; ++nt) {
                    int rl = wm*32 + mt*16 + (lane >> 2);
                    int cl = wn*48 + nt*8 + ((lane & 3) << 1);
                    size_t r0 = ((size_t)perm_s[rl]*LSEQ + t)*G3;
                    size_t r1 = ((size_t)perm_s[rl+8]*LSEQ + t)*G3;
                    *(float2*)&GI2[r0 + cb2 + cl] = make_float2(c[mt][nt][0], c[mt][nt][1]);
                    *(float2*)&GI2[r1 + cb2 + cl] = make_float2(c[mt][nt][2], c[mt][nt][3]);
                }
        }
    }
}

// ---------------- tail: fused [self|FL] @ Wf^T (K=512) ----------------
__global__ __launch_bounds__(256) void sgemm_cat(
    const float* __restrict__ self_x, const float* __restrict__ FL,
    const float* __restrict__ Wf, float* __restrict__ C)
{
    __shared__ float As[32][68];
    __shared__ float Bs[32][68];
    const int tid = threadIdx.x;
    const int tx = tid & 15, ty = tid >> 4;
    const int mb = blockIdx.x * 64, nb = blockIdx.y * 64;
    const int K = 2*HD;

    float2 acc[4][2];
    #pragma unroll
    for (int i = 0; i < 4; ++i) { acc[i][0] = make_float2(0.f,0.f); acc[i][1] = make_float2(0.f,0.f); }

    for (int kc = 0; kc < K; kc += 32) {
        #pragma unroll
        for (int q = 0; q < 2; ++q) {
            int idx = q*256 + tid;
            int row = idx >> 3;
            int k4  = (idx & 7) << 2;
            const int m = mb + row;
            const int k = kc + k4;
            const float4 v = (kc < HD)
                ? *reinterpret_cast<const float4*>(&self_x[(size_t)(m >> 5)*HD + k])
                : *reinterpret_cast<const float4*>(&FL[(size_t)m*HD + (k - HD)]);
            As[k4+0][row] = v.x; As[k4+1][row] = v.y; As[k4+2][row] = v.z; As[k4+3][row] = v.w;
        }
        #pragma unroll
        for (int q = 0; q < 2; ++q) {
            int idx = q*256 + tid;
            int n  = idx >> 3;
            int k4 = (idx & 7) << 2;
            const float4 v = *reinterpret_cast<const float4*>(&Wf[(size_t)(nb+n)*K + kc + k4]);
            Bs[k4+0][n] = v.x; Bs[k4+1][n] = v.y; Bs[k4+2][n] = v.z; Bs[k4+3][n] = v.w;
        }
        __syncthreads();
        #pragma unroll
        for (int k = 0; k < 32; ++k) {
            const float4 a4 = *reinterpret_cast<const float4*>(&As[k][ty<<2]);
            const float4 b4 = *reinterpret_cast<const float4*>(&Bs[k][tx<<2]);
            const float2 b0 = make_float2(b4.x, b4.y);
            const float2 b1 = make_float2(b4.z, b4.w);
            float av[4] = {a4.x, a4.y, a4.z, a4.w};
            #pragma unroll
            for (int i = 0; i < 4; ++i) {
                float2 aa = make_float2(av[i], av[i]);
                acc[i][0] = ffma2(aa, b0, acc[i][0]);
                acc[i][1] = ffma2(aa, b1, acc[i][1]);
            }
        }
        __syncthreads();
    }
    #pragma unroll
    for (int i = 0; i < 4; ++i) {
        const int row = mb + (ty<<2) + i;
        float4 o;
        o.x = acc[i][0].x; o.y = acc[i][0].y; o.z = acc[i][1].x; o.w = acc[i][1].y;
        *reinterpret_cast<float4*>(&C[(size_t)row*HD + nb + (tx<<2)]) = o;
    }
}

// ---------------- fp32 tail GEMM: V = SF @ Wb (W[k*N+n]) ----------------
__global__ __launch_bounds__(256) void sgemm_tw(
    const float* __restrict__ A, const float* __restrict__ W, float* __restrict__ C)
{
    __shared__ float As[32][68];
    __shared__ float Bs[32][68];
    const int tid = threadIdx.x;
    const int tx = tid & 15, ty = tid >> 4;
    const int mb = blockIdx.x * 64, nb = blockIdx.y * 64;
    const int K = HD, N = HD;

    float2 acc[4][2];
    #pragma unroll
    for (int i = 0; i < 4; ++i) { acc[i][0] = make_float2(0.f,0.f); acc[i][1] = make_float2(0.f,0.f); }

    for (int kc = 0; kc < K; kc += 32) {
        #pragma unroll
        for (int q = 0; q < 2; ++q) {
            int idx = q*256 + tid;
            int row = idx >> 3;
            int k4  = (idx & 7) << 2;
            const float4 v = *reinterpret_cast<const float4*>(&A[(size_t)(mb+row)*K + kc + k4]);
            As[k4+0][row] = v.x; As[k4+1][row] = v.y; As[k4+2][row] = v.z; As[k4+3][row] = v.w;
        }
        #pragma unroll
        for (int q = 0; q < 2; ++q) {
            int idx = q*256 + tid;
            int k  = idx >> 4;
            int n4 = (idx & 15) << 2;
            const float4 v = *reinterpret_cast<const float4*>(&W[(size_t)(kc+k)*N + nb + n4]);
            *reinterpret_cast<float4*>(&Bs[k][n4]) = v;
        }
        __syncthreads();
        #pragma unroll
        for (int k = 0; k < 32; ++k) {
            const float4 a4 = *reinterpret_cast<const float4*>(&As[k][ty<<2]);
            const float4 b4 = *reinterpret_cast<const float4*>(&Bs[k][tx<<2]);
            const float2 b0 = make_float2(b4.x, b4.y);
            const float2 b1 = make_float2(b4.z, b4.w);
            float av[4] = {a4.x, a4.y, a4.z, a4.w};
            #pragma unroll
            for (int i = 0; i < 4; ++i) {
                float2 aa = make_float2(av[i], av[i]);
                acc[i][0] = ffma2(aa, b0, acc[i][0]);
                acc[i][1] = ffma2(aa, b1, acc[i][1]);
            }
        }
        __syncthreads();
    }
    #pragma unroll
    for (int i = 0; i < 4; ++i) {
        const int row = mb + (ty<<2) + i;
        float4 o;
        o.x = acc[i][0].x; o.y = acc[i][0].y; o.z = acc[i][1].x; o.w = acc[i][1].y;
        *reinterpret_cast<float4*>(&C[(size_t)row*N + nb + (tx<<2)]) = o;
    }
}

__global__ __launch_bounds__(256) void tf_kernel(
    const float* __restrict__ common_x, const float* __restrict__ common_time,
    const float* __restrict__ V, const int* __restrict__ clen, float* __restrict__ TF)
{
    const int m = blockIdx.x;
    __shared__ float vs[HD];
    __shared__ float wsum[8];
    const int tid = threadIdx.x;
    vs[tid] = V[(size_t)m*HD + tid];
    __syncthreads();
    const int warp = tid >> 5, lane = tid & 31;
    const int cl = clen[m];
    float acc = 0.f;
    for (int s = warp; s < cl; s += 8) {
        const float* cx = common_x + ((size_t)m*SSEQ + s)*HD;
        float p = 0.f;
        #pragma unroll
        for (int q = 0; q < 8; ++q) p += cx[lane + 32*q] * vs[lane + 32*q];
        #pragma unroll
        for (int off = 16; off; off >>= 1) p += __shfl_xor_sync(0xffffffffu, p, off);
        if (lane == 0)
            acc += softplus_f(p) * expf(-common_time[(size_t)m*SSEQ + s]);
    }
    if (lane == 0) wsum[warp] = acc;
    __syncthreads();
    if (tid == 0) {
        float s = 0.f;
        for (int w = 0; w < 8; ++w) s += wsum[w];
        TF[m] = s;
    }
}

__global__ __launch_bounds__(256) void out_kernel(
    const float* __restrict__ TF, const float* __restrict__ FL,
    const int* __restrict__ fnum, float* __restrict__ out)
{
    const int b = blockIdx.x;
    __shared__ float w[MAXF];
    const int tid = threadIdx.x;
    const int fn = fnum[b];
    if (tid < MAXF) w[tid] = (tid < fn) ? TF[b*MAXF + tid] : 0.f;
    __syncthreads();
    if (tid == 0) {
        float mx = w[0];
        for (int f = 1; f < MAXF; ++f) mx = fmaxf(mx, w[f]);
        float s = 0.f;
        for (int f = 0; f < MAXF; ++f) { float e = expf(w[f] - mx); w[f] = e; s += e; }
        float inv = 1.f / s;
        for (int f = 0; f < MAXF; ++f) w[f] *= inv;
    }
    __syncthreads();
    float acc = 0.f;
    for (int f = 0; f < fn; ++f)
        acc += w[f] * FL[(size_t)(b*MAXF + f)*HD + tid];
    out[(size_t)b*HD + tid] = acc;
}

// ---------------- host launcher ----------------
extern "C" void kernel_launch(void* const* d_in, const int* in_sizes, int n_in,
                              void* d_out, int out_size)
{
    const float* self_x      = (const float*)d_in[0];
    const float* common_x    = (const float*)d_in[1];
    const float* common_time = (const float*)d_in[2];
    const float* friend_x    = (const float*)d_in[3];
    const float* Wih0 = (const float*)d_in[4];
    const float* Whh0 = (const float*)d_in[5];
    const float* bih0 = (const float*)d_in[6];
    const float* bhh0 = (const float*)d_in[7];
    const float* Wih1 = (const float*)d_in[8];
    const float* Whh1 = (const float*)d_in[9];
    const float* bih1 = (const float*)d_in[10];
    const float* bhh1 = (const float*)d_in[11];
    const float* Wf   = (const float*)d_in[12];
    const float* Wb   = (const float*)d_in[13];
    const int*   flen = (const int*)d_in[14];
    const int*   fnum = (const int*)d_in[15];
    const int*   clen = (const int*)d_in[16];
    float* out = (float*)d_out;

    float *GI, *GI2, *FL, *SF, *V, *TF;
    __nv_bfloat16 *Hh, *Hl, *FXh, *FXl, *X1h, *X1l, *Wh, *Wl;
    cudaGetSymbolAddress((void**)&Hh,  g_Hh);
    cudaGetSymbolAddress((void**)&Hl,  g_Hl);
    cudaGetSymbolAddress((void**)&GI,  g_GI);
    cudaGetSymbolAddress((void**)&GI2, g_GI2);
    cudaGetSymbolAddress((void**)&FXh, g_FXh);
    cudaGetSymbolAddress((void**)&FXl, g_FXl);
    cudaGetSymbolAddress((void**)&X1h, g_X1h);
    cudaGetSymbolAddress((void**)&X1l, g_X1l);
    cudaGetSymbolAddress((void**)&Wh,  g_Wh);
    cudaGetSymbolAddress((void**)&Wl,  g_Wl);
    cudaGetSymbolAddress((void**)&FL,  g_FL);
    cudaGetSymbolAddress((void**)&SF,  g_SF);
    cudaGetSymbolAddress((void**)&V,   g_V);
    cudaGetSymbolAddress((void**)&TF,  g_TF);

    const float* Wsrc[4] = {Wih0, Whh0, Wih1, Whh1};

    static bool init_done = false;
    if (!init_done) {
        cudaFuncSetAttribute(hmma_big,       cudaFuncAttributeMaxDynamicSharedMemorySize, BIG_DYN);
        cudaFuncSetAttribute(gru_persist<0>, cudaFuncAttributeMaxDynamicSharedMemorySize, GRU_DYN);
        cudaFuncSetAttribute(gru_persist<1>, cudaFuncAttributeMaxDynamicSharedMemorySize, GRU_DYN);
        init_done = true;
    }

    // --- sort rows by flen + reset counters/queue ---
    rank_kernel<<<NSEQ/256, 256>>>(flen);

    // --- conversions ---
    split_fx<<<((size_t)MTOT*HD + 255)/256, 256>>>(friend_x, FXh, FXl, flen);
    for (int w = 0; w < 4; ++w)
        split_kernel<<<(G3*HD + 255)/256, 256>>>(Wsrc[w], Wh + (size_t)w*G3*HD,
                                                 Wl + (size_t)w*G3*HD, G3*HD);

    // ---- layer 0 big GEMM ----
    hmma_big<<<dim3(8, 16, LSEQ), 256, BIG_DYN>>>(FXh, FXl,
        Wh + 0*(size_t)G3*HD, Wl + 0*(size_t)G3*HD, GI);

    // ---- layer 0 recurrence + embedded layer-1 x-GEMM (work stealing) ----
    gru_persist<0><<<dim3(16, 8), 256, GRU_DYN>>>(
        Wh + 1*(size_t)G3*HD, Wl + 1*(size_t)G3*HD, GI,
        Hh, Hl, X1h, X1l, nullptr, flen, bih0, bhh0,
        Wh + 2*(size_t)G3*HD, Wl + 2*(size_t)G3*HD, GI2);

    // ---- layer 1 recurrence (GI2 fully materialized by kernel above) ----
    gru_persist<1><<<dim3(16, 8), 256, GRU_DYN>>>(
        Wh + 3*(size_t)G3*HD, Wl + 3*(size_t)G3*HD, GI2,
        Hh, Hl, nullptr, nullptr, FL, flen, bih1, bhh1,
        nullptr, nullptr, nullptr);

    // ---- tail ----
    sgemm_cat<<<dim3(NSEQ/64, HD/64), 256>>>(self_x, FL, Wf, SF);
    sgemm_tw<<<dim3(NSEQ/64, HD/64), 256>>>(SF, Wb, V);
    tf_kernel<<<NSEQ, 256>>>(common_x, common_time, V, clen, TF);
    out_kernel<<<NBATCH, 256>>>(TF, FL, fnum, out);
}

// round 17
// speedup vs baseline: 1.1392x; 1.0189x over previous
#include <cuda_runtime.h>
#include <cuda_bf16.h>
#include <cstdint>
#include <math.h>

#define HD    256
#define LSEQ  50
#define SSEQ  50
#define NBATCH 64
#define MAXF  32
#define NSEQ  (NBATCH*MAXF)            // 2048
#define MTOT  (NSEQ*LSEQ)              // 102400
#define G3    (3*HD)                   // 768
#define NTILES (16*LSEQ*8)             // L1 GEMM tile space

// ---------------- device scratch ----------------
__device__ __nv_bfloat16  g_Hh[2][NSEQ*HD];
__device__ __nv_bfloat16  g_Hl[2][NSEQ*HD];
__device__ float          g_GI[(size_t)MTOT*G3];    // layer-0 pre-activations
__device__ float          g_GI2[(size_t)MTOT*G3];   // layer-1 pre-activations
__device__ __nv_bfloat16  g_FXh[(size_t)MTOT*HD];
__device__ __nv_bfloat16  g_FXl[(size_t)MTOT*HD];
__device__ __nv_bfloat16  g_X1h[(size_t)MTOT*HD];
__device__ __nv_bfloat16  g_X1l[(size_t)MTOT*HD];
__device__ __nv_bfloat16  g_Wh[4][G3*HD];
__device__ __nv_bfloat16  g_Wl[4][G3*HD];
__device__ float g_FL[NSEQ*HD];
__device__ float g_SF[NSEQ*HD];
__device__ float g_V[NSEQ*HD];
__device__ float g_TF[NSEQ];
__device__ unsigned g_cnt[32];            // rowgroup step counters (16 per layer)
__device__ unsigned g_work;               // L1 GEMM tile queue head
__device__ int g_perm[NSEQ];
__device__ int g_gmax[16];

// ---------------- helpers ----------------
__device__ __forceinline__ float fast_sigmoid(float x){
    return __fdividef(1.f, 1.f + __expf(-x));
}
__device__ __forceinline__ float fast_tanh(float x){
    return 1.f - __fdividef(2.f, __expf(2.f*x) + 1.f);
}
__device__ __forceinline__ float softplus_f(float x){
    return (x > 20.f) ? x : log1pf(expf(x));
}
__device__ __forceinline__ float2 ffma2(float2 a, float2 b, float2 c){
    unsigned long long ua = reinterpret_cast<unsigned long long&>(a);
    unsigned long long ub = reinterpret_cast<unsigned long long&>(b);
    unsigned long long uc = reinterpret_cast<unsigned long long&>(c);
    unsigned long long ud;
    asm("fma.rn.f32x2 %0, %1, %2, %3;" : "=l"(ud) : "l"(ua), "l"(ub), "l"(uc));
    return reinterpret_cast<float2&>(ud);
}
__device__ __forceinline__ uint32_t smem_u32(const void* p){
    return (uint32_t)__cvta_generic_to_shared(p);
}
__device__ __forceinline__ void ldsm_x4(unsigned* r, uint32_t addr){
    asm volatile("ldmatrix.sync.aligned.m8n8.x4.shared.b16 {%0,%1,%2,%3}, [%4];\n"
        : "=r"(r[0]), "=r"(r[1]), "=r"(r[2]), "=r"(r[3]) : "r"(addr));
}
__device__ __forceinline__ void mma16816(float* c, const unsigned* a, const unsigned* b){
    asm volatile("mma.sync.aligned.m16n8k16.row.col.f32.bf16.bf16.f32 "
        "{%0,%1,%2,%3}, {%4,%5,%6,%7}, {%8,%9}, {%0,%1,%2,%3};\n"
        : "+f"(c[0]), "+f"(c[1]), "+f"(c[2]), "+f"(c[3])
        : "r"(a[0]), "r"(a[1]), "r"(a[2]), "r"(a[3]), "r"(b[0]), "r"(b[1]));
}
__device__ __forceinline__ unsigned ld_acq(const unsigned* p){
    unsigned v;
    asm volatile("ld.acquire.gpu.u32 %0, [%1];" : "=r"(v) : "l"(p) : "memory");
    return v;
}
__device__ __forceinline__ void red_release(unsigned* p){
    asm volatile("red.release.gpu.global.add.u32 [%0], %1;" :: "l"(p), "r"(1u) : "memory");
}
__device__ __forceinline__ void cp16(uint32_t dst, const void* src){
    asm volatile("cp.async.cg.shared.global [%0], [%1], 16;" :: "r"(dst), "l"(src) : "memory");
}
#define CP_COMMIT() asm volatile("cp.async.commit_group;" ::: "memory")
#define CP_WAIT1()  asm volatile("cp.async.wait_group 1;" ::: "memory")
#define CP_WAIT0()  asm volatile("cp.async.wait_group 0;" ::: "memory")

// ---------------- sort rows by flen (descending, deterministic) ----------------
__global__ void rank_kernel(const int* __restrict__ flen){
    __shared__ int fl_s[NSEQ];
    for (int i = threadIdx.x; i < NSEQ; i += 256) fl_s[i] = flen[i];
    __syncthreads();
    const int i = blockIdx.x*256 + threadIdx.x;
    const int f = fl_s[i];
    int r = 0;
    for (int jj = 0; jj < NSEQ; ++jj) {
        int fj = fl_s[jj];
        r += (fj > f) || (fj == f && jj < i);
    }
    g_perm[r] = i;
    if ((r & 127) == 0) g_gmax[r >> 7] = f;
    if (blockIdx.x == 0 && threadIdx.x < 32) g_cnt[threadIdx.x] = 0u;
    if (blockIdx.x == 0 && threadIdx.x == 0) g_work = 0u;
}

// ---------------- staging (cp.async) ----------------
__device__ __forceinline__ void stageA_seq(uint32_t sA_h, uint32_t sA_l,
        const __nv_bfloat16* __restrict__ Ah, const __nv_bfloat16* __restrict__ Al,
        const int* __restrict__ perm_s, int t, int kk, int tid){
    #pragma unroll
    for (int q = 0; q < 2; ++q) {
        int idx = q*256 + tid;
        int r = idx >> 2, ks = (idx & 3) << 3;
        size_t s = ((size_t)perm_s[r]*LSEQ + t)*HD + kk + ks;
        uint32_t d = (uint32_t)(r*40 + ks)*2u;
        cp16(sA_h + d, Ah + s);
        cp16(sA_l + d, Al + s);
    }
}
__device__ __forceinline__ void stageA_row(uint32_t sA_h, uint32_t sA_l,
        const __nv_bfloat16* __restrict__ Ah, const __nv_bfloat16* __restrict__ Al,
        const int* __restrict__ perm_s, int kk, int tid){
    #pragma unroll
    for (int q = 0; q < 2; ++q) {
        int idx = q*256 + tid;
        int r = idx >> 2, ks = (idx & 3) << 3;
        size_t s = (size_t)perm_s[r]*HD + kk + ks;
        uint32_t d = (uint32_t)(r*40 + ks)*2u;
        cp16(sA_h + d, Ah + s);
        cp16(sA_l + d, Al + s);
    }
}
__device__ __forceinline__ void stageB_cp(uint32_t sB_h, uint32_t sB_l,
        const __nv_bfloat16* __restrict__ Bh, const __nv_bfloat16* __restrict__ Bl,
        int ubu, int kk, int tid){
    #pragma unroll
    for (int q = 0; q < 2; ++q) {
        int idx = q*256 + tid;
        if (idx < 384) {
            int p = idx >> 2, ks = (idx & 3) << 3;
            int w = (p >> 5)*HD + ubu + (p & 31);
            size_t s = (size_t)w*HD + kk + ks;
            uint32_t d = (uint32_t)(p*40 + ks)*2u;
            cp16(sB_h + d, Bh + s);
            cp16(sB_l + d, Bl + s);
        }
    }
}
__device__ __forceinline__ void stageGI_piece(uint32_t cs, const float* __restrict__ GI,
        const int* __restrict__ perm_s, int t, size_t colbase, int piece, int tid){
    #pragma unroll
    for (int q = 0; q < 2; ++q) {
        int i = q*256 + tid;
        if (i < 384) {
            int i2 = piece*384 + i;
            int rl = i2 / 24, c16 = i2 % 24;
            const float* src = GI + ((size_t)perm_s[rl]*LSEQ + t)*G3 + colbase + c16*4;
            cp16(cs + (uint32_t)(rl*128 + c16*4)*4u, src);
        }
    }
}

// ---------------- MMA on one staged 32-k chunk (3-term hi/lo) ----------------
__device__ __forceinline__ void mma_chunk(
    float (&c)[2][6][4],
    uint32_t aAsh, uint32_t aAsl, uint32_t aBsh, uint32_t aBsl,
    int a_m, int a_k, int b_n, int b_k, int wm, int wn, int bstride, int bkoff)
{
    #pragma unroll
    for (int kt = 0; kt < 2; ++kt) {
        unsigned ah[2][4], al[2][4], bh[3][4], bl[3][4];
        #pragma unroll
        for (int mt = 0; mt < 2; ++mt) {
            uint32_t off = 2u*((wm*32 + mt*16 + a_m)*40 + kt*16 + a_k);
            ldsm_x4(ah[mt], aAsh + off);
            ldsm_x4(al[mt], aAsl + off);
        }
        #pragma unroll
        for (int np = 0; np < 3; ++np) {
            uint32_t off = 2u*((wn*48 + np*16 + b_n)*bstride + bkoff + kt*16 + b_k);
            ldsm_x4(bh[np], aBsh + off);
            ldsm_x4(bl[np], aBsl + off);
        }
        #pragma unroll
        for (int mt = 0; mt < 2; ++mt)
            #pragma unroll
            for (int nt = 0; nt < 6; ++nt) {
                const unsigned* B1 = &bh[nt>>1][(nt&1)*2];
                const unsigned* B2 = &bl[nt>>1][(nt&1)*2];
                mma16816(c[mt][nt], ah[mt], B1);
                mma16816(c[mt][nt], al[mt], B1);
                mma16816(c[mt][nt], ah[mt], B2);
            }
    }
}

// ---------------- hi/lo split conversions (vectorized) ----------------
__global__ void splitW2(const float* __restrict__ w0,
                        __nv_bfloat16* __restrict__ h0, __nv_bfloat16* __restrict__ l0,
                        const float* __restrict__ w1,
                        __nv_bfloat16* __restrict__ h1, __nv_bfloat16* __restrict__ l1){
    const int i4 = blockIdx.x*256 + threadIdx.x;          // float4 index over 2 matrices
    const int n4 = (G3*HD)/4;
    const float* src; __nv_bfloat16 *dh, *dl; int off;
    if (i4 < n4) { src = w0; dh = h0; dl = l0; off = i4*4; }
    else         { src = w1; dh = h1; dl = l1; off = (i4 - n4)*4; }
    float4 v = *reinterpret_cast<const float4*>(src + off);
    float vv[4] = {v.x, v.y, v.z, v.w};
    __align__(8) __nv_bfloat16 hh[4], ll[4];
    #pragma unroll
    for (int e = 0; e < 4; ++e) {
        hh[e] = __float2bfloat16(vv[e]);
        ll[e] = __float2bfloat16(vv[e] - __bfloat162float(hh[e]));
    }
    *reinterpret_cast<uint2*>(dh + off) = *reinterpret_cast<uint2*>(hh);
    *reinterpret_cast<uint2*>(dl + off) = *reinterpret_cast<uint2*>(ll);
}

__global__ void split_fx(const float* __restrict__ x,
                         __nv_bfloat16* __restrict__ hi,
                         __nv_bfloat16* __restrict__ lo,
                         const int* __restrict__ flen){
    const size_t i = ((size_t)blockIdx.x*256 + threadIdx.x) * 4;
    const int t   = (int)((i >> 8) % LSEQ);
    const int row = (int)(i / ((size_t)LSEQ*HD));
    if (t >= flen[row]) return;
    float4 v = *reinterpret_cast<const float4*>(x + i);
    float vv[4] = {v.x, v.y, v.z, v.w};
    __align__(8) __nv_bfloat16 hh[4], ll[4];
    #pragma unroll
    for (int e = 0; e < 4; ++e) {
        hh[e] = __float2bfloat16(vv[e]);
        ll[e] = __float2bfloat16(vv[e] - __bfloat162float(hh[e]));
    }
    *reinterpret_cast<uint2*>(hi + i) = *reinterpret_cast<uint2*>(hh);
    *reinterpret_cast<uint2*>(lo + i) = *reinterpret_cast<uint2*>(ll);
}

// =====================================================================
// Big x-GEMM (layer 0), cp.async double-buffered, 2 CTAs/SM.
// grid (8 units, 16 seqgroups, 50 t); early exit when t >= gmax[sg].
// =====================================================================
#define BIG_ASH 0u
#define BIG_ASL 20480u
#define BIG_BSH 40960u
#define BIG_BSL 56320u
#define BIG_DYN 71680u

__global__ __launch_bounds__(256, 2) void hmma_big(
    const __nv_bfloat16* __restrict__ Ah, const __nv_bfloat16* __restrict__ Al,
    const __nv_bfloat16* __restrict__ Bh, const __nv_bfloat16* __restrict__ Bl,
    float* __restrict__ GI)
{
    const int sg = blockIdx.y;
    const int t  = blockIdx.z;
    if (t >= g_gmax[sg]) return;

    extern __shared__ char smraw[];
    __shared__ int perm_s[128];
    const uint32_t sb = smem_u32(smraw);
    const int tid  = threadIdx.x;
    const int lane = tid & 31, warp = tid >> 5;
    const int wm = warp >> 1, wn = warp & 1;
    const int ubu = blockIdx.x * 32;

    if (tid < 128) perm_s[tid] = g_perm[sg*128 + tid];
    __syncthreads();

    const int grp = lane >> 3, rr = lane & 7;
    const int a_m = (grp & 1)*8 + rr, a_k = (grp >> 1)*8;
    const int b_n = (grp >> 1)*8 + rr, b_k = (grp & 1)*8;

    float c[2][6][4];
    #pragma unroll
    for (int mt = 0; mt < 2; ++mt)
        #pragma unroll
        for (int nt = 0; nt < 6; ++nt)
            #pragma unroll
            for (int q = 0; q < 4; ++q) c[mt][nt][q] = 0.f;

    stageA_seq(sb + BIG_ASH, sb + BIG_ASL, Ah, Al, perm_s, t, 0, tid);
    stageB_cp(sb + BIG_BSH, sb + BIG_BSL, Bh, Bl, ubu, 0, tid);
    CP_COMMIT();

    for (int kc = 0; kc < 8; ++kc) {
        const int buf = kc & 1;
        if (kc < 7) {
            const int nb = buf ^ 1;
            stageA_seq(sb + BIG_ASH + nb*10240u, sb + BIG_ASL + nb*10240u,
                       Ah, Al, perm_s, t, (kc+1)*32, tid);
            stageB_cp(sb + BIG_BSH + nb*7680u, sb + BIG_BSL + nb*7680u,
                      Bh, Bl, ubu, (kc+1)*32, tid);
            CP_COMMIT();
            CP_WAIT1();
        } else {
            CP_WAIT0();
        }
        __syncthreads();
        mma_chunk(c, sb + BIG_ASH + buf*10240u, sb + BIG_ASL + buf*10240u,
                     sb + BIG_BSH + buf*7680u,  sb + BIG_BSL + buf*7680u,
                  a_m, a_k, b_n, b_k, wm, wn, 40, 0);
        __syncthreads();
    }

    const size_t colbase = (size_t)blockIdx.x * 96;
    #pragma unroll
    for (int mt = 0; mt < 2; ++mt)
        #pragma unroll
        for (int nt = 0; nt < 6; ++nt) {
            int rl = wm*32 + mt*16 + (lane >> 2);
            int cl = wn*48 + nt*8 + ((lane & 3) << 1);
            size_t r0 = ((size_t)perm_s[rl]*LSEQ + t)*G3;
            size_t r1 = ((size_t)perm_s[rl+8]*LSEQ + t)*G3;
            *(float2*)&GI[r0 + colbase + cl] = make_float2(c[mt][nt][0], c[mt][nt][1]);
            *(float2*)&GI[r1 + colbase + cl] = make_float2(c[mt][nt][2], c[mt][nt][3]);
        }
}

// =====================================================================
// Persistent GRU recurrence (per-rowgroup step bound gmax[rg]).
// LAYER 0: after the recurrence, CTAs steal layer-1 x-GEMM tiles from a
// global queue, gated on the resident rowgroup counters.
// =====================================================================
#define GRU_BSH 0u
#define GRU_BSL 50688u
#define GRU_ASH 101376u
#define GRU_ASL 121856u
#define GRU_CS  142336u
#define GRU_DYN 207872u
#define SM_B_STRIDE 264
#define STL_BH  GRU_CS
#define STL_BL  (GRU_CS + 15360u)

template<int LAYER>
__global__ __launch_bounds__(256) void gru_persist(
    const __nv_bfloat16* __restrict__ Whh_h, const __nv_bfloat16* __restrict__ Whh_l,
    const float* __restrict__ GI,
    __nv_bfloat16* __restrict__ Hhb, __nv_bfloat16* __restrict__ Hlb,
    __nv_bfloat16* __restrict__ X1h, __nv_bfloat16* __restrict__ X1l,
    float* __restrict__ FL, const int* __restrict__ flen,
    const float* __restrict__ bih, const float* __restrict__ bhh,
    const __nv_bfloat16* __restrict__ sBh, const __nv_bfloat16* __restrict__ sBl,
    float* __restrict__ GI2)
{
    extern __shared__ char smraw[];
    __shared__ int perm_s[128];
    __shared__ int flen_s[128];
    __shared__ unsigned widx_s;
    const uint32_t sb = smem_u32(smraw);
    float* Cs = (float*)(smraw + GRU_CS);
    const uint32_t csb = sb + GRU_CS;
    unsigned short* Bsh = (unsigned short*)(smraw + GRU_BSH);
    unsigned short* Bsl = (unsigned short*)(smraw + GRU_BSL);

    const int tid  = threadIdx.x;
    const int lane = tid & 31, warp = tid >> 5;
    const int wm = warp >> 1, wn = warp & 1;
    const int rg   = blockIdx.x;
    const int ubu  = blockIdx.y * 32;
    const int tmax = g_gmax[rg];

    if (tid < 128) {
        int p = g_perm[rg*128 + tid];
        perm_s[tid] = p;
        flen_s[tid] = flen[p];
    }

    const int grp = lane >> 3, rr = lane & 7;
    const int a_m = (grp & 1)*8 + rr, a_k = (grp >> 1)*8;
    const int b_n = (grp >> 1)*8 + rr, b_k = (grp & 1)*8;

    // ---- load Whh tile once ----
    for (int idx = tid; idx < 96*32; idx += 256) {
        int p = idx >> 5, ks = (idx & 31) << 3;
        int w = (p >> 5)*HD + ubu + (p & 31);
        *(uint4*)&Bsh[p*SM_B_STRIDE + ks] = *(const uint4*)&Whh_h[(size_t)w*HD + ks];
        *(uint4*)&Bsl[p*SM_B_STRIDE + ks] = *(const uint4*)&Whh_l[(size_t)w*HD + ks];
    }
    __syncthreads();

    const int jl = tid & 31;
    const int j  = ubu + jl;
    const float b_r  = bih[j]      + bhh[j];
    const float b_z  = bih[HD+j]   + bhh[HD+j];
    const float bi_n = bih[2*HD+j];
    const float bh_n = bhh[2*HD+j];
    const size_t colbase = (size_t)blockIdx.y * 96;
    unsigned* cnt = &g_cnt[rg + (LAYER ? 16 : 0)];

    for (int t = 0; t < tmax; ++t) {
        const int pa = t & 1, pb = (t+1) & 1;
        const __nv_bfloat16* Ahp = Hhb + (size_t)pa*NSEQ*HD;
        const __nv_bfloat16* Alp = Hlb + (size_t)pa*NSEQ*HD;
        __nv_bfloat16* Hnh = Hhb + (size_t)pb*NSEQ*HD;
        __nv_bfloat16* Hnl = Hlb + (size_t)pb*NSEQ*HD;

        float c[2][6][4];
        #pragma unroll
        for (int mt = 0; mt < 2; ++mt)
            #pragma unroll
            for (int nt = 0; nt < 6; ++nt)
                #pragma unroll
                for (int q = 0; q < 4; ++q) c[mt][nt][q] = 0.f;

        if (t > 0) {
            stageA_row(sb + GRU_ASH, sb + GRU_ASL, Ahp, Alp, perm_s, 0, tid);
            stageGI_piece(csb, GI, perm_s, t, colbase, 0, tid);
            CP_COMMIT();
            for (int kc = 0; kc < 8; ++kc) {
                const int buf = kc & 1;
                if (kc < 7) {
                    const int nb = buf ^ 1;
                    stageA_row(sb + GRU_ASH + nb*10240u, sb + GRU_ASL + nb*10240u,
                               Ahp, Alp, perm_s, (kc+1)*32, tid);
                    stageGI_piece(csb, GI, perm_s, t, colbase, kc+1, tid);
                    CP_COMMIT();
                    CP_WAIT1();
                } else {
                    CP_WAIT0();
                }
                __syncthreads();
                mma_chunk(c, sb + GRU_ASH + buf*10240u, sb + GRU_ASL + buf*10240u,
                             sb + GRU_BSH, sb + GRU_BSL,
                          a_m, a_k, b_n, b_k, wm, wn, SM_B_STRIDE, kc*32);
                __syncthreads();
            }
        } else {
            #pragma unroll
            for (int pc = 0; pc < 8; ++pc)
                stageGI_piece(csb, GI, perm_s, t, colbase, pc, tid);
            CP_COMMIT();
            CP_WAIT0();
            __syncthreads();
        }

        // ---- merge fragments: r/z add into Cs, n store to hh_n column ----
        #pragma unroll
        for (int mt = 0; mt < 2; ++mt)
            #pragma unroll
            for (int nt = 0; nt < 6; ++nt) {
                int rl = wm*32 + mt*16 + (lane >> 2);
                int cl = wn*48 + nt*8 + ((lane & 3) << 1);
                const bool is_n = (cl >= 64);
                const int ccl = is_n ? cl + 32 : cl;
                float2* p0 = (float2*)&Cs[rl*128 + ccl];
                float2* p1 = (float2*)&Cs[(rl+8)*128 + ccl];
                if (is_n) {
                    *p0 = make_float2(c[mt][nt][0], c[mt][nt][1]);
                    *p1 = make_float2(c[mt][nt][2], c[mt][nt][3]);
                } else {
                    float2 v0 = *p0, v1 = *p1;
                    *p0 = make_float2(v0.x + c[mt][nt][0], v0.y + c[mt][nt][1]);
                    *p1 = make_float2(v1.x + c[mt][nt][2], v1.y + c[mt][nt][3]);
                }
            }
        __syncthreads();

        // ---- gate epilogue ----
        #pragma unroll
        for (int i = 0; i < 16; ++i) {
            const int rl  = (tid >> 5) + i*8;
            const int row = perm_s[rl];
            const float r = fast_sigmoid(Cs[rl*128 + jl]      + b_r);
            const float z = fast_sigmoid(Cs[rl*128 + 32 + jl] + b_z);
            const float n = fast_tanh(Cs[rl*128 + 64 + jl] + bi_n +
                                      r*(Cs[rl*128 + 96 + jl] + bh_n));
            float hp = 0.f;
            if (t > 0)
                hp = __bfloat162float(Ahp[(size_t)row*HD + j]) +
                     __bfloat162float(Alp[(size_t)row*HD + j]);
            const float h  = (1.f - z)*n + z*hp;
            __nv_bfloat16 hh = __float2bfloat16(h);
            __nv_bfloat16 hl = __float2bfloat16(h - __bfloat162float(hh));
            Hnh[(size_t)row*HD + j] = hh;
            Hnl[(size_t)row*HD + j] = hl;
            if (LAYER == 0) {
                if (t < flen_s[rl]) {            // dead X1 slots stay zero
                    size_t xi = ((size_t)row*LSEQ + t)*HD + j;
                    X1h[xi] = hh; X1l[xi] = hl;
                }
            } else {
                if (t == flen_s[rl] - 1) FL[(size_t)row*HD + j] = h;
            }
        }

        // ---- rowgroup barrier: always release (consumed by stealers), wait unless last ----
        __threadfence();
        __syncthreads();
        if (tid == 0) {
            red_release(cnt);
            if (t + 1 < tmax) {
                const unsigned target = 8u*(unsigned)(t+1);
                while (ld_acq(cnt) < target) __nanosleep(32);
            }
        }
        __syncthreads();
    }

    // =============== LAYER 0: steal layer-1 x-GEMM tiles ===============
    if (LAYER == 0) {
        for (;;) {
            __syncthreads();
            if (tid == 0) widx_s = atomicAdd(&g_work, 1u);
            __syncthreads();
            const unsigned widx = widx_s;
            if (widx >= (unsigned)NTILES) break;
            const int t   = (int)(widx / 128u);      // t ascending: matches availability
            const int sg  = (int)((widx / 8u) % 16u);
            const int ubx = (int)(widx % 8u);
            if (t >= g_gmax[sg]) continue;

            if (tid == 0) {
                const unsigned target = 8u*(unsigned)(t+1);
                while (ld_acq(&g_cnt[sg]) < target) __nanosleep(64);
            }
            if (tid < 128) perm_s[tid] = g_perm[sg*128 + tid];
            __syncthreads();

            float c[2][6][4];
            #pragma unroll
            for (int mt = 0; mt < 2; ++mt)
                #pragma unroll
                for (int nt = 0; nt < 6; ++nt)
                    #pragma unroll
                    for (int q = 0; q < 4; ++q) c[mt][nt][q] = 0.f;

            stageA_seq(sb + GRU_ASH, sb + GRU_ASL, X1h, X1l, perm_s, t, 0, tid);
            stageB_cp(sb + STL_BH, sb + STL_BL, sBh, sBl, ubx*32, 0, tid);
            CP_COMMIT();
            for (int kc = 0; kc < 8; ++kc) {
                const int buf = kc & 1;
                if (kc < 7) {
                    const int nb = buf ^ 1;
                    stageA_seq(sb + GRU_ASH + nb*10240u, sb + GRU_ASL + nb*10240u,
                               X1h, X1l, perm_s, t, (kc+1)*32, tid);
                    stageB_cp(sb + STL_BH + nb*7680u, sb + STL_BL + nb*7680u,
                              sBh, sBl, ubx*32, (kc+1)*32, tid);
                    CP_COMMIT();
                    CP_WAIT1();
                } else {
                    CP_WAIT0();
                }
                __syncthreads();
                mma_chunk(c, sb + GRU_ASH + buf*10240u, sb + GRU_ASL + buf*10240u,
                             sb + STL_BH + buf*7680u,  sb + STL_BL + buf*7680u,
                          a_m, a_k, b_n, b_k, wm, wn, 40, 0);
                __syncthreads();
            }

            const size_t cb2 = (size_t)ubx * 96;
            #pragma unroll
            for (int mt = 0; mt < 2; ++mt)
                #pragma unroll
                for (int nt = 0; nt < 6; ++nt) {
                    int rl = wm*32 + mt*16 + (lane >> 2);
                    int cl = wn*48 + nt*8 + ((lane & 3) << 1);
                    size_t r0 = ((size_t)perm_s[rl]*LSEQ + t)*G3;
                    size_t r1 = ((size_t)perm_s[rl+8]*LSEQ + t)*G3;
                    *(float2*)&GI2[r0 + cb2 + cl] = make_float2(c[mt][nt][0], c[mt][nt][1]);
                    *(float2*)&GI2[r1 + cb2 + cl] = make_float2(c[mt][nt][2], c[mt][nt][3]);
                }
        }
    }
}

// ---------------- tail: fused [self|FL] @ Wf^T (K=512) ----------------
__global__ __launch_bounds__(256) void sgemm_cat(
    const float* __restrict__ self_x, const float* __restrict__ FL,
    const float* __restrict__ Wf, float* __restrict__ C)
{
    __shared__ float As[32][68];
    __shared__ float Bs[32][68];
    const int tid = threadIdx.x;
    const int tx = tid & 15, ty = tid >> 4;
    const int mb = blockIdx.x * 64, nb = blockIdx.y * 64;
    const int K = 2*HD;

    float2 acc[4][2];
    #pragma unroll
    for (int i = 0; i < 4; ++i) { acc[i][0] = make_float2(0.f,0.f); acc[i][1] = make_float2(0.f,0.f); }

    for (int kc = 0; kc < K; kc += 32) {
        #pragma unroll
        for (int q = 0; q < 2; ++q) {
            int idx = q*256 + tid;
            int row = idx >> 3;
            int k4  = (idx & 7) << 2;
            const int m = mb + row;
            const int k = kc + k4;
            const float4 v = (kc < HD)
                ? *reinterpret_cast<const float4*>(&self_x[(size_t)(m >> 5)*HD + k])
                : *reinterpret_cast<const float4*>(&FL[(size_t)m*HD + (k - HD)]);
            As[k4+0][row] = v.x; As[k4+1][row] = v.y; As[k4+2][row] = v.z; As[k4+3][row] = v.w;
        }
        #pragma unroll
        for (int q = 0; q < 2; ++q) {
            int idx = q*256 + tid;
            int n  = idx >> 3;
            int k4 = (idx & 7) << 2;
            const float4 v = *reinterpret_cast<const float4*>(&Wf[(size_t)(nb+n)*K + kc + k4]);
            Bs[k4+0][n] = v.x; Bs[k4+1][n] = v.y; Bs[k4+2][n] = v.z; Bs[k4+3][n] = v.w;
        }
        __syncthreads();
        #pragma unroll
        for (int k = 0; k < 32; ++k) {
            const float4 a4 = *reinterpret_cast<const float4*>(&As[k][ty<<2]);
            const float4 b4 = *reinterpret_cast<const float4*>(&Bs[k][tx<<2]);
            const float2 b0 = make_float2(b4.x, b4.y);
            const float2 b1 = make_float2(b4.z, b4.w);
            float av[4] = {a4.x, a4.y, a4.z, a4.w};
            #pragma unroll
            for (int i = 0; i < 4; ++i) {
                float2 aa = make_float2(av[i], av[i]);
                acc[i][0] = ffma2(aa, b0, acc[i][0]);
                acc[i][1] = ffma2(aa, b1, acc[i][1]);
            }
        }
        __syncthreads();
    }
    #pragma unroll
    for (int i = 0; i < 4; ++i) {
        const int row = mb + (ty<<2) + i;
        float4 o;
        o.x = acc[i][0].x; o.y = acc[i][0].y; o.z = acc[i][1].x; o.w = acc[i][1].y;
        *reinterpret_cast<float4*>(&C[(size_t)row*HD + nb + (tx<<2)]) = o;
    }
}

// ---------------- fp32 tail GEMM: V = SF @ Wb (W[k*N+n]) ----------------
__global__ __launch_bounds__(256) void sgemm_tw(
    const float* __restrict__ A, const float* __restrict__ W, float* __restrict__ C)
{
    __shared__ float As[32][68];
    __shared__ float Bs[32][68];
    const int tid = threadIdx.x;
    const int tx = tid & 15, ty = tid >> 4;
    const int mb = blockIdx.x * 64, nb = blockIdx.y * 64;
    const int K = HD, N = HD;

    float2 acc[4][2];
    #pragma unroll
    for (int i = 0; i < 4; ++i) { acc[i][0] = make_float2(0.f,0.f); acc[i][1] = make_float2(0.f,0.f); }

    for (int kc = 0; kc < K; kc += 32) {
        #pragma unroll
        for (int q = 0; q < 2; ++q) {
            int idx = q*256 + tid;
            int row = idx >> 3;
            int k4  = (idx & 7) << 2;
            const float4 v = *reinterpret_cast<const float4*>(&A[(size_t)(mb+row)*K + kc + k4]);
            As[k4+0][row] = v.x; As[k4+1][row] = v.y; As[k4+2][row] = v.z; As[k4+3][row] = v.w;
        }
        #pragma unroll
        for (int q = 0; q < 2; ++q) {
            int idx = q*256 + tid;
            int k  = idx >> 4;
            int n4 = (idx & 15) << 2;
            const float4 v = *reinterpret_cast<const float4*>(&W[(size_t)(kc+k)*N + nb + n4]);
            *reinterpret_cast<float4*>(&Bs[k][n4]) = v;
        }
        __syncthreads();
        #pragma unroll
        for (int k = 0; k < 32; ++k) {
            const float4 a4 = *reinterpret_cast<const float4*>(&As[k][ty<<2]);
            const float4 b4 = *reinterpret_cast<const float4*>(&Bs[k][tx<<2]);
            const float2 b0 = make_float2(b4.x, b4.y);
            const float2 b1 = make_float2(b4.z, b4.w);
            float av[4] = {a4.x, a4.y, a4.z, a4.w};
            #pragma unroll
            for (int i = 0; i < 4; ++i) {
                float2 aa = make_float2(av[i], av[i]);
                acc[i][0] = ffma2(aa, b0, acc[i][0]);
                acc[i][1] = ffma2(aa, b1, acc[i][1]);
            }
        }
        __syncthreads();
    }
    #pragma unroll
    for (int i = 0; i < 4; ++i) {
        const int row = mb + (ty<<2) + i;
        float4 o;
        o.x = acc[i][0].x; o.y = acc[i][0].y; o.z = acc[i][1].x; o.w = acc[i][1].y;
        *reinterpret_cast<float4*>(&C[(size_t)row*N + nb + (tx<<2)]) = o;
    }
}

__global__ __launch_bounds__(256) void tf_kernel(
    const float* __restrict__ common_x, const float* __restrict__ common_time,
    const float* __restrict__ V, const int* __restrict__ clen, float* __restrict__ TF)
{
    const int m = blockIdx.x;
    __shared__ float vs[HD];
    __shared__ float wsum[8];
    const int tid = threadIdx.x;
    vs[tid] = V[(size_t)m*HD + tid];
    __syncthreads();
    const int warp = tid >> 5, lane = tid & 31;
    const int cl = clen[m];
    float acc = 0.f;
    for (int s = warp; s < cl; s += 8) {
        const float* cx = common_x + ((size_t)m*SSEQ + s)*HD;
        float p = 0.f;
        #pragma unroll
        for (int q = 0; q < 8; ++q) p += cx[lane + 32*q] * vs[lane + 32*q];
        #pragma unroll
        for (int off = 16; off; off >>= 1) p += __shfl_xor_sync(0xffffffffu, p, off);
        if (lane == 0)
            acc += softplus_f(p) * expf(-common_time[(size_t)m*SSEQ + s]);
    }
    if (lane == 0) wsum[warp] = acc;
    __syncthreads();
    if (tid == 0) {
        float s = 0.f;
        for (int w = 0; w < 8; ++w) s += wsum[w];
        TF[m] = s;
    }
}

__global__ __launch_bounds__(256) void out_kernel(
    const float* __restrict__ TF, const float* __restrict__ FL,
    const int* __restrict__ fnum, float* __restrict__ out)
{
    const int b = blockIdx.x;
    __shared__ float w[MAXF];
    const int tid = threadIdx.x;
    const int fn = fnum[b];
    if (tid < MAXF) w[tid] = (tid < fn) ? TF[b*MAXF + tid] : 0.f;
    __syncthreads();
    if (tid == 0) {
        float mx = w[0];
        for (int f = 1; f < MAXF; ++f) mx = fmaxf(mx, w[f]);
        float s = 0.f;
        for (int f = 0; f < MAXF; ++f) { float e = expf(w[f] - mx); w[f] = e; s += e; }
        float inv = 1.f / s;
        for (int f = 0; f < MAXF; ++f) w[f] *= inv;
    }
    __syncthreads();
    float acc = 0.f;
    for (int f = 0; f < fn; ++f)
        acc += w[f] * FL[(size_t)(b*MAXF + f)*HD + tid];
    out[(size_t)b*HD + tid] = acc;
}

// ---------------- host launcher ----------------
extern "C" void kernel_launch(void* const* d_in, const int* in_sizes, int n_in,
                              void* d_out, int out_size)
{
    const float* self_x      = (const float*)d_in[0];
    const float* common_x    = (const float*)d_in[1];
    const float* common_time = (const float*)d_in[2];
    const float* friend_x    = (const float*)d_in[3];
    const float* Wih0 = (const float*)d_in[4];
    const float* Whh0 = (const float*)d_in[5];
    const float* bih0 = (const float*)d_in[6];
    const float* bhh0 = (const float*)d_in[7];
    const float* Wih1 = (const float*)d_in[8];
    const float* Whh1 = (const float*)d_in[9];
    const float* bih1 = (const float*)d_in[10];
    const float* bhh1 = (const float*)d_in[11];
    const float* Wf   = (const float*)d_in[12];
    const float* Wb   = (const float*)d_in[13];
    const int*   flen = (const int*)d_in[14];
    const int*   fnum = (const int*)d_in[15];
    const int*   clen = (const int*)d_in[16];
    float* out = (float*)d_out;

    float *GI, *GI2, *FL, *SF, *V, *TF;
    __nv_bfloat16 *Hh, *Hl, *FXh, *FXl, *X1h, *X1l, *Wh, *Wl;
    cudaGetSymbolAddress((void**)&Hh,  g_Hh);
    cudaGetSymbolAddress((void**)&Hl,  g_Hl);
    cudaGetSymbolAddress((void**)&GI,  g_GI);
    cudaGetSymbolAddress((void**)&GI2, g_GI2);
    cudaGetSymbolAddress((void**)&FXh, g_FXh);
    cudaGetSymbolAddress((void**)&FXl, g_FXl);
    cudaGetSymbolAddress((void**)&X1h, g_X1h);
    cudaGetSymbolAddress((void**)&X1l, g_X1l);
    cudaGetSymbolAddress((void**)&Wh,  g_Wh);
    cudaGetSymbolAddress((void**)&Wl,  g_Wl);
    cudaGetSymbolAddress((void**)&FL,  g_FL);
    cudaGetSymbolAddress((void**)&SF,  g_SF);
    cudaGetSymbolAddress((void**)&V,   g_V);
    cudaGetSymbolAddress((void**)&TF,  g_TF);

    static bool init_done = false;
    if (!init_done) {
        cudaFuncSetAttribute(hmma_big,       cudaFuncAttributeMaxDynamicSharedMemorySize, BIG_DYN);
        cudaFuncSetAttribute(gru_persist<0>, cudaFuncAttributeMaxDynamicSharedMemorySize, GRU_DYN);
        cudaFuncSetAttribute(gru_persist<1>, cudaFuncAttributeMaxDynamicSharedMemorySize, GRU_DYN);
        init_done = true;
    }

    // Launch order matters for ncu -s 5 -c 1: gru_persist<0> is launch #6.
    // (1) rank
    rank_kernel<<<NSEQ/256, 256>>>(flen);
    // (2) split friend_x (vectorized, dead-skip)
    split_fx<<<((size_t)MTOT*HD/4 + 255)/256, 256>>>(friend_x, FXh, FXl, flen);
    // (3)(4) split weights, 2 matrices per launch (vectorized)
    const int wblocks = (2*G3*HD/4 + 255)/256;
    splitW2<<<wblocks, 256>>>(Wih0, Wh + 0*(size_t)G3*HD, Wl + 0*(size_t)G3*HD,
                              Whh0, Wh + 1*(size_t)G3*HD, Wl + 1*(size_t)G3*HD);
    splitW2<<<wblocks, 256>>>(Wih1, Wh + 2*(size_t)G3*HD, Wl + 2*(size_t)G3*HD,
                              Whh1, Wh + 3*(size_t)G3*HD, Wl + 3*(size_t)G3*HD);

    // (5) layer 0 big GEMM
    hmma_big<<<dim3(8, 16, LSEQ), 256, BIG_DYN>>>(FXh, FXl,
        Wh + 0*(size_t)G3*HD, Wl + 0*(size_t)G3*HD, GI);

    // (6) layer 0 recurrence + embedded layer-1 x-GEMM (work stealing)  [PROFILED]
    gru_persist<0><<<dim3(16, 8), 256, GRU_DYN>>>(
        Wh + 1*(size_t)G3*HD, Wl + 1*(size_t)G3*HD, GI,
        Hh, Hl, X1h, X1l, nullptr, flen, bih0, bhh0,
        Wh + 2*(size_t)G3*HD, Wl + 2*(size_t)G3*HD, GI2);

    // (7) layer 1 recurrence
    gru_persist<1><<<dim3(16, 8), 256, GRU_DYN>>>(
        Wh + 3*(size_t)G3*HD, Wl + 3*(size_t)G3*HD, GI2,
        Hh, Hl, nullptr, nullptr, FL, flen, bih1, bhh1,
        nullptr, nullptr, nullptr);

    // ---- tail ----
    sgemm_cat<<<dim3(NSEQ/64, HD/64), 256>>>(self_x, FL, Wf, SF);
    sgemm_tw<<<dim3(NSEQ/64, HD/64), 256>>>(SF, Wb, V);
    tf_kernel<<<NSEQ, 256>>>(common_x, common_time, V, clen, TF);
    out_kernel<<<NBATCH, 256>>>(TF, FL, fnum, out);
}